// round 14
// baseline (speedup 1.0000x reference)
#include <cuda_runtime.h>
#include <cuda_fp16.h>
#include <math.h>
#include <stdint.h>

#define BATCH 8
#define SEQ   512
#define HDIM  1024
#define FFDIM 4096
#define NHEAD 16
#define DHEAD 64
#define MROWS (BATCH*SEQ)   // 4096

// ---------------------------------------------------------------------------
// Static device scratch
// ---------------------------------------------------------------------------
__device__ float g_t1[(size_t)MROWS * HDIM];
__device__ float g_attn[(size_t)MROWS * HDIM];

__device__ __half g_xh[(size_t)MROWS * HDIM];
__device__ __half g_qh[(size_t)MROWS * HDIM];       // Q (prescaled 0.125)
__device__ __half g_kh[(size_t)MROWS * HDIM];
__device__ __half g_vh[(size_t)MROWS * HDIM];
__device__ __half g_ctx[(size_t)MROWS * HDIM];
__device__ __half g_attnh[(size_t)MROWS * HDIM];
__device__ __half g_inter[(size_t)MROWS * FFDIM];
__device__ __half g_adder[(size_t)BATCH * SEQ * SEQ];

__device__ __half g_wqkv[(size_t)3 * HDIM * HDIM];  // packed, transposed [N,K]
__device__ __half g_wao[(size_t)HDIM * HDIM];
__device__ __half g_wi[(size_t)FFDIM * HDIM];
__device__ __half g_wo[(size_t)HDIM * FFDIM];

__device__ __forceinline__ float gelu_tanh(float x) {
    float x3 = x * x * x;
    return 0.5f * x * (1.0f + tanhf(0.7978845608028654f * (x + 0.044715f * x3)));
}
__device__ __forceinline__ uint32_t h2_as_u32(__half2 h) {
    union { __half2 h2; uint32_t u; } c; c.h2 = h; return c.u;
}

// ---------------------------------------------------------------------------
// PTX helpers. NOTE: ldm/mma are intentionally NON-volatile so the compiler
// may software-pipeline MMAs across fragment loads. ldm keeps a "memory"
// clobber so it cannot cross __syncthreads / cp.async boundaries; mma is a
// pure register op ordered by data dependences alone.
// ---------------------------------------------------------------------------
__device__ __forceinline__ uint32_t smem_u32(const void* p) {
    uint32_t a;
    asm("{ .reg .u64 t; cvta.to.shared.u64 t, %1; cvt.u32.u64 %0, t; }"
        : "=r"(a) : "l"(p));
    return a;
}
__device__ __forceinline__ void cp16(uint32_t saddr, const void* gaddr) {
    asm volatile("cp.async.cg.shared.global [%0], [%1], 16;" :: "r"(saddr), "l"(gaddr));
}
#define CP_COMMIT() asm volatile("cp.async.commit_group;" ::: "memory")
#define CP_WAIT(n)  asm volatile("cp.async.wait_group %0;" :: "n"(n) : "memory")

__device__ __forceinline__ void ldm_x4(uint32_t* r, uint32_t addr) {
    asm("ldmatrix.sync.aligned.m8n8.x4.shared.b16 {%0,%1,%2,%3}, [%4];"
        : "=r"(r[0]), "=r"(r[1]), "=r"(r[2]), "=r"(r[3]) : "r"(addr) : "memory");
}
__device__ __forceinline__ void ldm_x4_t(uint32_t* r, uint32_t addr) {
    asm("ldmatrix.sync.aligned.m8n8.x4.trans.shared.b16 {%0,%1,%2,%3}, [%4];"
        : "=r"(r[0]), "=r"(r[1]), "=r"(r[2]), "=r"(r[3]) : "r"(addr) : "memory");
}
__device__ __forceinline__ void mma_f16(float* c, const uint32_t* a, const uint32_t* b) {
    asm("mma.sync.aligned.m16n8k16.row.col.f32.f16.f16.f32 "
        "{%0,%1,%2,%3}, {%4,%5,%6,%7}, {%8,%9}, {%0,%1,%2,%3};"
        : "+f"(c[0]), "+f"(c[1]), "+f"(c[2]), "+f"(c[3])
        : "r"(a[0]), "r"(a[1]), "r"(a[2]), "r"(a[3]), "r"(b[0]), "r"(b[1]));
}

// ---------------------------------------------------------------------------
// Unified prep kernel (R12, proven)
// ---------------------------------------------------------------------------
#define PREP_BLOCKS 18432

__global__ __launch_bounds__(256)
void prep_kernel(const float* __restrict__ inp, const int* __restrict__ mask,
                 const float* __restrict__ Wq, const float* __restrict__ Wk,
                 const float* __restrict__ Wv, const float* __restrict__ Wao,
                 const float* __restrict__ Wi, const float* __restrict__ Wo,
                 __half* __restrict__ xh, __half* __restrict__ adder,
                 __half* __restrict__ wqkv, __half* __restrict__ wao,
                 __half* __restrict__ wi, __half* __restrict__ wo)
{
    __shared__ float tile[32][33];
    const int bid = blockIdx.x;
    const int t = threadIdx.x;

    if (bid < 4096) {
        int i = bid * 256 + t;
        float4 v = ((const float4*)inp)[i];
        union { __half2 h2[2]; uint2 u; } p;
        p.h2[0] = __floats2half2_rn(v.x, v.y);
        p.h2[1] = __floats2half2_rn(v.z, v.w);
        ((uint2*)xh)[i] = p.u;
        return;
    }
    if (bid < 6144) {
        int i = (bid - 4096) * 256 + t;
        int4 v = ((const int4*)mask)[i];
        union { __half2 h2[2]; uint2 u; } p;
        p.h2[0] = __floats2half2_rn((1.0f - (float)v.x) * -10000.0f,
                                    (1.0f - (float)v.y) * -10000.0f);
        p.h2[1] = __floats2half2_rn((1.0f - (float)v.z) * -10000.0f,
                                    (1.0f - (float)v.w) * -10000.0f);
        ((uint2*)adder)[i] = p.u;
        return;
    }

    const float* W;
    __half* T;
    int K, N, lb;
    if (bid < 7168)       { W = Wq;  T = wqkv;                          K = HDIM;  N = HDIM;  lb = bid - 6144; }
    else if (bid < 8192)  { W = Wk;  T = wqkv + (size_t)HDIM * HDIM;    K = HDIM;  N = HDIM;  lb = bid - 7168; }
    else if (bid < 9216)  { W = Wv;  T = wqkv + (size_t)2 * HDIM * HDIM;K = HDIM;  N = HDIM;  lb = bid - 8192; }
    else if (bid < 10240) { W = Wao; T = wao;                           K = HDIM;  N = HDIM;  lb = bid - 9216; }
    else if (bid < 14336) { W = Wi;  T = wi;                            K = HDIM;  N = FFDIM; lb = bid - 10240; }
    else                  { W = Wo;  T = wo;                            K = FFDIM; N = HDIM;  lb = bid - 14336; }

    const int nbx = N / 32;
    const int bx = lb % nbx;
    const int by = lb / nbx;
    const int tx = t & 31;
    const int ty = t >> 5;

    const int x = bx * 32 + tx;
    const int y0 = by * 32;
    #pragma unroll
    for (int j = 0; j < 32; j += 8)
        tile[ty + j][tx] = W[(size_t)(y0 + ty + j) * N + x];
    __syncthreads();

    const int k = y0 + tx;
    #pragma unroll
    for (int j = 0; j < 32; j += 8) {
        int n = bx * 32 + ty + j;
        T[(size_t)n * K + k] = __float2half_rn(tile[tx][ty + j]);
    }
}

// ---------------------------------------------------------------------------
// fp16 GEMM via mma.sync. CTA 128x128, 4 warps (2x2), warp tile 64x64.
// KC=64, 3-stage cp.async, XOR-swizzled 128B rows, interleaved prefetch
// slices (R13), non-volatile ldm/mma (R14).
// ---------------------------------------------------------------------------
#define KC 64
#define TILE_B 16384                     // 128 rows x 128 B
#define STAGE_B (2 * TILE_B)             // 32768
#define GEMM_SMEM (3 * STAGE_B)          // 98304

#define SWZ(r, c) ((uint32_t)(r) * 128 + ((uint32_t)((c) ^ ((r) & 7)) * 16))

template<int MODE>
__global__ __launch_bounds__(128, 2)
void mma_gemm(const __half* __restrict__ A, const __half* __restrict__ Bm,
              const float* __restrict__ bias, const float* __restrict__ bias2,
              const float* __restrict__ bias3, const float* __restrict__ res,
              float* __restrict__ Cf, __half* __restrict__ Ch,
              __half* __restrict__ Ch2, __half* __restrict__ Ch3,
              int M, int N, int K, int do_gelu, float oscale)
{
    extern __shared__ char sm[];
    const uint32_t sbase = smem_u32(sm);

    const int t    = threadIdx.x;
    const int lane = t & 31;
    const int w    = t >> 5;          // 0..3
    const int wm   = w & 1;           // 2 row groups (64)
    const int wn   = w >> 1;          // 2 col groups (64)
    const int row0 = blockIdx.y * 128;
    const int col0 = blockIdx.x * 128;

    const int NC = K / KC;

    const int l_r = t >> 3;
    const int l_c = t & 7;

    const int a_r  = wm * 64 + (lane & 15);
    const int a_ch = lane >> 4;
    const int b_r  = wn * 64 + (lane >> 4) * 8 + (lane & 7);   // + p*16
    const int b_ch = (lane >> 3) & 1;

    float acc[4][8][4];
    #pragma unroll
    for (int i = 0; i < 4; i++)
        #pragma unroll
        for (int j = 0; j < 8; j++)
            #pragma unroll
            for (int e = 0; e < 4; e++) acc[i][j][e] = 0.0f;

    // prologue: chunks 0,1
    #pragma unroll
    for (int pc = 0; pc < 2; pc++) {
        const int kofs = pc * KC;
        const uint32_t bb = sbase + pc * STAGE_B;
        #pragma unroll
        for (int j = 0; j < 8; j++) {
            int r = l_r + j * 16;
            uint32_t sw = SWZ(r, l_c);
            cp16(bb + sw,          A  + (size_t)(row0 + r) * K + kofs + l_c * 8);
            cp16(bb + TILE_B + sw, Bm + (size_t)(col0 + r) * K + kofs + l_c * 8);
        }
        CP_COMMIT();
    }

    uint32_t af[2][4][4];
    uint32_t bf[2][16];

    for (int i = 0; i < NC; i++) {
        CP_WAIT(1);
        __syncthreads();

        const uint32_t baseA = sbase + (i % 3) * STAGE_B;
        const uint32_t baseB = baseA + TILE_B;
        const bool do_pf = (i + 2 < NC);
        const int kofs = (i + 2) * KC;
        const uint32_t pb = sbase + ((i + 2) % 3) * STAGE_B;
        const __half* pA = A  + (size_t)(row0 + l_r) * K + kofs + l_c * 8;
        const __half* pB = Bm + (size_t)(col0 + l_r) * K + kofs + l_c * 8;

        #pragma unroll
        for (int p = 0; p < 4; p++)
            ldm_x4(&bf[0][p * 4], baseB + SWZ(b_r + p * 16, b_ch));
        #pragma unroll
        for (int mt = 0; mt < 4; mt++)
            ldm_x4(af[0][mt], baseA + SWZ(a_r + mt * 16, a_ch));

        #pragma unroll
        for (int ks = 0; ks < 4; ks++) {
            const int cur = ks & 1, nxt = cur ^ 1;

            if (do_pf) {
                #pragma unroll
                for (int jj = 0; jj < 2; jj++) {
                    int j = ks * 2 + jj;
                    int r = l_r + j * 16;
                    uint32_t sw = SWZ(r, l_c);
                    cp16(pb + sw,          pA + (size_t)(j * 16) * K);
                    cp16(pb + TILE_B + sw, pB + (size_t)(j * 16) * K);
                }
            }

            if (ks < 3) {
                #pragma unroll
                for (int p = 0; p < 4; p++)
                    ldm_x4(&bf[nxt][p * 4],
                           baseB + SWZ(b_r + p * 16, (ks + 1) * 2 + b_ch));
                #pragma unroll
                for (int mt = 0; mt < 4; mt++)
                    ldm_x4(af[nxt][mt],
                           baseA + SWZ(a_r + mt * 16, (ks + 1) * 2 + a_ch));
            }
            #pragma unroll
            for (int mt = 0; mt < 4; mt++)
                #pragma unroll
                for (int nt = 0; nt < 8; nt++)
                    mma_f16(acc[mt][nt], af[cur][mt], &bf[cur][nt * 2]);
        }
        CP_COMMIT();
    }

    const int qr = lane >> 2;
    const int qc = (lane & 3) * 2;

    if (MODE == 1) {
        const int seg = col0 >> 10;                       // 0=Q, 1=K, 2=V
        const float* bseg = (seg == 0) ? bias : (seg == 1) ? bias2 : bias3;
        __half* outp      = (seg == 0) ? Ch   : (seg == 1) ? Ch2   : Ch3;
        const float osc   = (seg == 0) ? 0.125f : 1.0f;
        #pragma unroll
        for (int mt = 0; mt < 4; mt++) {
            #pragma unroll
            for (int nt = 0; nt < 8; nt++) {
                const int gr0 = row0 + wm * 64 + mt * 16 + qr;
                const int gcl = (col0 & 1023) + wn * 64 + nt * 8 + qc;
                float2 bv = *(const float2*)(bseg + gcl);
                *(__half2*)(outp + (size_t)gr0 * HDIM + gcl) =
                    __floats2half2_rn((acc[mt][nt][0] + bv.x) * osc,
                                      (acc[mt][nt][1] + bv.y) * osc);
                *(__half2*)(outp + (size_t)(gr0 + 8) * HDIM + gcl) =
                    __floats2half2_rn((acc[mt][nt][2] + bv.x) * osc,
                                      (acc[mt][nt][3] + bv.y) * osc);
            }
        }
        return;
    }

    #pragma unroll
    for (int mt = 0; mt < 4; mt++) {
        #pragma unroll
        for (int nt = 0; nt < 8; nt++) {
            const int gr0 = row0 + wm * 64 + mt * 16 + qr;
            const int gc  = col0 + wn * 64 + nt * 8 + qc;
            float2 bv = *(const float2*)(bias + gc);
            float o0 = (acc[mt][nt][0] + bv.x) * oscale;
            float o1 = (acc[mt][nt][1] + bv.y) * oscale;
            float o2 = (acc[mt][nt][2] + bv.x) * oscale;
            float o3 = (acc[mt][nt][3] + bv.y) * oscale;
            if (res) {
                float2 r0v = *(const float2*)(res + (size_t)gr0 * N + gc);
                float2 r1v = *(const float2*)(res + (size_t)(gr0 + 8) * N + gc);
                o0 += r0v.x; o1 += r0v.y; o2 += r1v.x; o3 += r1v.y;
            }
            if (do_gelu) {
                o0 = gelu_tanh(o0); o1 = gelu_tanh(o1);
                o2 = gelu_tanh(o2); o3 = gelu_tanh(o3);
            }
            if (Cf) {
                *(float2*)(Cf + (size_t)gr0 * N + gc)       = make_float2(o0, o1);
                *(float2*)(Cf + (size_t)(gr0 + 8) * N + gc) = make_float2(o2, o3);
            } else {
                *(__half2*)(Ch + (size_t)gr0 * N + gc)       = __floats2half2_rn(o0, o1);
                *(__half2*)(Ch + (size_t)(gr0 + 8) * N + gc) = __floats2half2_rn(o2, o3);
            }
        }
    }
}

// ---------------------------------------------------------------------------
// Tensor-core flash attention (fp16 mma, fp32 softmax/accum).
// ---------------------------------------------------------------------------
#define ALDA 72
#define SQ_OFF   0
#define SK_OFF   9216
#define SV_OFF   36864
#define SAD_OFF  64512
#define ATTN_SMEM 89088

__global__ __launch_bounds__(128)
void attn_kernel(const __half* __restrict__ Qg, const __half* __restrict__ Kg,
                 const __half* __restrict__ Vg, const __half* __restrict__ ADg,
                 __half* __restrict__ O)
{
    extern __shared__ char sm[];
    const uint32_t sbase = smem_u32(sm);

    const int t = threadIdx.x;
    const int lane = t & 31;
    const int w = t >> 5;
    const int b = blockIdx.z, h = blockIdx.y;
    const int q0 = blockIdx.x * 64;

    const int qr = lane >> 2;
    const int qc = (lane & 3) * 2;

    const int lr = t >> 1;
    const int lc2 = (t & 1) * 4;

    auto issue = [&](int ic) {
        const int slot = ic % 3;
        const int kc = ic * 64;
        const __half* kg = Kg + (size_t)(b * SEQ + kc + lr) * HDIM + h * DHEAD;
        const __half* vg = Vg + (size_t)(b * SEQ + kc + lr) * HDIM + h * DHEAD;
        const __half* ag = ADg + (size_t)(b * SEQ + q0 + lr) * SEQ + kc;
        uint32_t ks = sbase + SK_OFF + slot * 9216 + lr * (ALDA * 2);
        uint32_t vs = sbase + SV_OFF + slot * 9216 + lr * (ALDA * 2);
        uint32_t as = sbase + SAD_OFF + slot * 8192 + lr * 128;
        #pragma unroll
        for (int c = 0; c < 4; c++) {
            cp16(ks + (lc2 + c) * 16, kg + (lc2 + c) * 8);
            cp16(vs + (lc2 + c) * 16, vg + (lc2 + c) * 8);
            cp16(as + (lc2 + c) * 16, ag + (lc2 + c) * 8);
        }
    };

    {
        const __half* qg = Qg + (size_t)(b * SEQ + q0 + lr) * HDIM + h * DHEAD;
        uint32_t qs = sbase + SQ_OFF + lr * (ALDA * 2);
        #pragma unroll
        for (int c = 0; c < 4; c++)
            cp16(qs + (lc2 + c) * 16, qg + (lc2 + c) * 8);
        issue(0);
        CP_COMMIT();
        issue(1);
        CP_COMMIT();
    }

    const int a_row = w * 16 + (lane & 15);
    const int a_col = (lane >> 4) * 8;
    const int b_nrow = (lane >> 4) * 8 + (lane & 7);
    const int b_kcol = ((lane >> 3) & 1) * 8;
    const int v_krow = lane & 15;
    const int v_ncol = (lane >> 4) * 8;

    uint32_t qf[4][4];
    float Oa[8][4];
    #pragma unroll
    for (int i = 0; i < 8; i++)
        #pragma unroll
        for (int e = 0; e < 4; e++) Oa[i][e] = 0.0f;
    float m0 = -1e30f, m1 = -1e30f, l0 = 0.0f, l1 = 0.0f;

    for (int ic = 0; ic < 8; ic++) {
        CP_WAIT(1);
        __syncthreads();

        if (ic == 0) {
            #pragma unroll
            for (int ks = 0; ks < 4; ks++) {
                uint32_t off = (uint32_t)a_row * (ALDA * 2) + (ks * 16 + a_col) * 2;
                ldm_x4(qf[ks], sbase + SQ_OFF + off);
            }
        }
        if (ic + 2 < 8) issue(ic + 2);
        CP_COMMIT();

        const int slot = ic % 3;
        const uint32_t baseK = sbase + SK_OFF + slot * 9216;
        const uint32_t baseV = sbase + SV_OFF + slot * 9216;
        const uint32_t baseAD = sbase + SAD_OFF + slot * 8192;

        float s[8][4];
        #pragma unroll
        for (int nt = 0; nt < 8; nt++) {
            uint32_t ad0 = (baseAD - sbase) + ((w * 16 + qr) * 64 + nt * 8 + qc) * 2;
            float2 f0 = __half22float2(*(const __half2*)(sm + ad0));
            float2 f1 = __half22float2(*(const __half2*)(sm + ad0 + 8 * 128));
            s[nt][0] = f0.x; s[nt][1] = f0.y;
            s[nt][2] = f1.x; s[nt][3] = f1.y;
        }
        #pragma unroll
        for (int nb = 0; nb < 4; nb++) {
            #pragma unroll
            for (int ks = 0; ks < 4; ks++) {
                uint32_t bfr[4];
                uint32_t off = (uint32_t)(nb * 16 + b_nrow) * (ALDA * 2)
                             + (ks * 16 + b_kcol) * 2;
                ldm_x4(bfr, baseK + off);
                mma_f16(s[2 * nb],     qf[ks], &bfr[0]);
                mma_f16(s[2 * nb + 1], qf[ks], &bfr[2]);
            }
        }

        float mx0 = -1e30f, mx1 = -1e30f;
        #pragma unroll
        for (int nt = 0; nt < 8; nt++) {
            mx0 = fmaxf(mx0, fmaxf(s[nt][0], s[nt][1]));
            mx1 = fmaxf(mx1, fmaxf(s[nt][2], s[nt][3]));
        }
        mx0 = fmaxf(mx0, __shfl_xor_sync(0xffffffffu, mx0, 1));
        mx0 = fmaxf(mx0, __shfl_xor_sync(0xffffffffu, mx0, 2));
        mx1 = fmaxf(mx1, __shfl_xor_sync(0xffffffffu, mx1, 1));
        mx1 = fmaxf(mx1, __shfl_xor_sync(0xffffffffu, mx1, 2));

        const float m0n = fmaxf(m0, mx0);
        const float m1n = fmaxf(m1, mx1);
        const float al0 = __expf(m0 - m0n);
        const float al1 = __expf(m1 - m1n);

        float sum0 = 0.0f, sum1 = 0.0f;
        uint32_t ph[4][4];
        #pragma unroll
        for (int j = 0; j < 4; j++) {
            float p00 = __expf(s[2 * j][0] - m0n);
            float p01 = __expf(s[2 * j][1] - m0n);
            float p02 = __expf(s[2 * j][2] - m1n);
            float p03 = __expf(s[2 * j][3] - m1n);
            float p10 = __expf(s[2 * j + 1][0] - m0n);
            float p11 = __expf(s[2 * j + 1][1] - m0n);
            float p12 = __expf(s[2 * j + 1][2] - m1n);
            float p13 = __expf(s[2 * j + 1][3] - m1n);
            sum0 += p00 + p01 + p10 + p11;
            sum1 += p02 + p03 + p12 + p13;
            ph[j][0] = h2_as_u32(__floats2half2_rn(p00, p01));
            ph[j][1] = h2_as_u32(__floats2half2_rn(p02, p03));
            ph[j][2] = h2_as_u32(__floats2half2_rn(p10, p11));
            ph[j][3] = h2_as_u32(__floats2half2_rn(p12, p13));
        }
        sum0 += __shfl_xor_sync(0xffffffffu, sum0, 1);
        sum0 += __shfl_xor_sync(0xffffffffu, sum0, 2);
        sum1 += __shfl_xor_sync(0xffffffffu, sum1, 1);
        sum1 += __shfl_xor_sync(0xffffffffu, sum1, 2);

        l0 = l0 * al0 + sum0;
        l1 = l1 * al1 + sum1;
        m0 = m0n; m1 = m1n;

        #pragma unroll
        for (int nt = 0; nt < 8; nt++) {
            Oa[nt][0] *= al0; Oa[nt][1] *= al0;
            Oa[nt][2] *= al1; Oa[nt][3] *= al1;
        }

        #pragma unroll
        for (int j = 0; j < 4; j++) {
            #pragma unroll
            for (int nt2 = 0; nt2 < 4; nt2++) {
                uint32_t vf[4];
                uint32_t off = (uint32_t)(j * 16 + v_krow) * (ALDA * 2)
                             + (nt2 * 16 + v_ncol) * 2;
                ldm_x4_t(vf, baseV + off);
                mma_f16(Oa[2 * nt2],     ph[j], &vf[0]);
                mma_f16(Oa[2 * nt2 + 1], ph[j], &vf[2]);
            }
        }
        __syncthreads();
    }

    const float inv0 = 1.0f / l0;
    const float inv1 = 1.0f / l1;
    const int gr0 = b * SEQ + q0 + w * 16 + qr;
    #pragma unroll
    for (int nt = 0; nt < 8; nt++) {
        const int gc = h * DHEAD + nt * 8 + qc;
        *(__half2*)(O + (size_t)gr0 * HDIM + gc) =
            __floats2half2_rn(Oa[nt][0] * inv0, Oa[nt][1] * inv0);
        *(__half2*)(O + (size_t)(gr0 + 8) * HDIM + gc) =
            __floats2half2_rn(Oa[nt][2] * inv1, Oa[nt][3] * inv1);
    }
}

// ---------------------------------------------------------------------------
// LayerNorm over rows of HDIM=1024; optional fp16 dual output.
// ---------------------------------------------------------------------------
__global__ __launch_bounds__(256)
void ln_kernel(const float* __restrict__ x, const float* __restrict__ gamma,
               const float* __restrict__ beta, float* __restrict__ y,
               __half* __restrict__ yh)
{
    const int row = blockIdx.x;
    const int t = threadIdx.x;
    const float* xr = x + (size_t)row * HDIM;

    float4 v = *(const float4*)(xr + t * 4);
    float s  = v.x + v.y + v.z + v.w;
    float s2 = v.x * v.x + v.y * v.y + v.z * v.z + v.w * v.w;

    #pragma unroll
    for (int o = 16; o > 0; o >>= 1) {
        s  += __shfl_xor_sync(0xffffffffu, s, o);
        s2 += __shfl_xor_sync(0xffffffffu, s2, o);
    }
    __shared__ float ws[8], ws2[8];
    const int w = t >> 5, lane = t & 31;
    if (lane == 0) { ws[w] = s; ws2[w] = s2; }
    __syncthreads();

    float ts = 0.0f, ts2 = 0.0f;
    #pragma unroll
    for (int i = 0; i < 8; i++) { ts += ws[i]; ts2 += ws2[i]; }

    const float mean = ts * (1.0f / HDIM);
    const float var  = ts2 * (1.0f / HDIM) - mean * mean;
    const float rstd = rsqrtf(var + 1e-12f);

    float4 g  = *(const float4*)(gamma + t * 4);
    float4 bb = *(const float4*)(beta  + t * 4);
    float4 o;
    o.x = (v.x - mean) * rstd * g.x + bb.x;
    o.y = (v.y - mean) * rstd * g.y + bb.y;
    o.z = (v.z - mean) * rstd * g.z + bb.z;
    o.w = (v.w - mean) * rstd * g.w + bb.w;
    *(float4*)(y + (size_t)row * HDIM + t * 4) = o;
    if (yh) {
        union { __half2 h2[2]; uint2 u; } p;
        p.h2[0] = __floats2half2_rn(o.x, o.y);
        p.h2[1] = __floats2half2_rn(o.z, o.w);
        ((uint2*)(yh + (size_t)row * HDIM))[t] = p.u;
    }
}

// ---------------------------------------------------------------------------
// Orchestration
// ---------------------------------------------------------------------------
extern "C" void kernel_launch(void* const* d_in, const int* in_sizes, int n_in,
                              void* d_out, int out_size)
{
    (void)in_sizes; (void)n_in; (void)out_size;

    const float* inp    = (const float*)d_in[0];
    const int*   mask   = (const int*)  d_in[1];
    const float* Wq     = (const float*)d_in[2];
    const float* bq     = (const float*)d_in[3];
    const float* Wk     = (const float*)d_in[4];
    const float* bk     = (const float*)d_in[5];
    const float* Wv     = (const float*)d_in[6];
    const float* bv     = (const float*)d_in[7];
    const float* Wao    = (const float*)d_in[8];
    const float* bao    = (const float*)d_in[9];
    const float* gamma1 = (const float*)d_in[10];
    const float* beta1  = (const float*)d_in[11];
    const float* Wi     = (const float*)d_in[12];
    const float* bi     = (const float*)d_in[13];
    const float* Wo     = (const float*)d_in[14];
    const float* bo     = (const float*)d_in[15];
    const float* gamma2 = (const float*)d_in[16];
    const float* beta2  = (const float*)d_in[17];
    float* out = (float*)d_out;

    float *t1, *attn;
    cudaGetSymbolAddress((void**)&t1,   g_t1);
    cudaGetSymbolAddress((void**)&attn, g_attn);

    __half *xh, *qh, *kh, *vh, *ctx, *attnh, *inter, *adder;
    __half *wqkv, *wao, *wi, *wo;
    cudaGetSymbolAddress((void**)&xh,    g_xh);
    cudaGetSymbolAddress((void**)&qh,    g_qh);
    cudaGetSymbolAddress((void**)&kh,    g_kh);
    cudaGetSymbolAddress((void**)&vh,    g_vh);
    cudaGetSymbolAddress((void**)&ctx,   g_ctx);
    cudaGetSymbolAddress((void**)&attnh, g_attnh);
    cudaGetSymbolAddress((void**)&inter, g_inter);
    cudaGetSymbolAddress((void**)&adder, g_adder);
    cudaGetSymbolAddress((void**)&wqkv, g_wqkv);
    cudaGetSymbolAddress((void**)&wao,  g_wao);
    cudaGetSymbolAddress((void**)&wi,   g_wi);
    cudaGetSymbolAddress((void**)&wo,   g_wo);

    cudaFuncSetAttribute(mma_gemm<0>, cudaFuncAttributeMaxDynamicSharedMemorySize, GEMM_SMEM);
    cudaFuncSetAttribute(mma_gemm<1>, cudaFuncAttributeMaxDynamicSharedMemorySize, GEMM_SMEM);
    cudaFuncSetAttribute(attn_kernel, cudaFuncAttributeMaxDynamicSharedMemorySize, ATTN_SMEM);

    dim3 blk256(256), blk128(128);

    dim3 gQKV(3 * HDIM / 128, MROWS / 128);   // 24 x 32
    dim3 gH(HDIM / 128, MROWS / 128);         // 8 x 32
    dim3 gF(FFDIM / 128, MROWS / 128);        // 32 x 32

    // ONE prep launch: input cvt + mask cvt + all 6 weight transposes
    prep_kernel<<<PREP_BLOCKS, blk256>>>(inp, mask, Wq, Wk, Wv, Wao, Wi, Wo,
                                         xh, adder, wqkv, wao, wi, wo);

    // fused QKV projection
    mma_gemm<1><<<gQKV, blk128, GEMM_SMEM>>>(xh, wqkv, bq, bk, bv, nullptr,
                                             nullptr, qh, kh, vh,
                                             MROWS, 3 * HDIM, HDIM, 0, 1.0f);

    // tensor-core flash attention -> fp16 ctx
    attn_kernel<<<dim3(SEQ / 64, NHEAD, BATCH), blk128, ATTN_SMEM>>>(qh, kh, vh, adder, ctx);

    // AO projection + residual, LN1
    mma_gemm<0><<<gH, blk128, GEMM_SMEM>>>(ctx, wao, bao, nullptr, nullptr, inp,
                                           t1, nullptr, nullptr, nullptr,
                                           MROWS, HDIM, HDIM, 0, 1.0f);
    ln_kernel<<<MROWS, blk256>>>(t1, gamma1, beta1, attn, attnh);

    // FFN
    mma_gemm<0><<<gF, blk128, GEMM_SMEM>>>(attnh, wi, bi, nullptr, nullptr, nullptr,
                                           nullptr, inter, nullptr, nullptr,
                                           MROWS, FFDIM, HDIM, 1, 1.0f);
    mma_gemm<0><<<gH, blk128, GEMM_SMEM>>>(inter, wo, bo, nullptr, nullptr, attn,
                                           t1, nullptr, nullptr, nullptr,
                                           MROWS, HDIM, FFDIM, 0, 1.0f);
    ln_kernel<<<MROWS, blk256>>>(t1, gamma2, beta2, out, nullptr);
}

// round 15
// speedup vs baseline: 1.0229x; 1.0229x over previous
#include <cuda_runtime.h>
#include <cuda_fp16.h>
#include <math.h>
#include <stdint.h>

#define BATCH 8
#define SEQ   512
#define HDIM  1024
#define FFDIM 4096
#define NHEAD 16
#define DHEAD 64
#define MROWS (BATCH*SEQ)   // 4096

// ---------------------------------------------------------------------------
// Static device scratch
// ---------------------------------------------------------------------------
__device__ float g_t1[(size_t)MROWS * HDIM];
__device__ float g_attn[(size_t)MROWS * HDIM];

__device__ __half g_xh[(size_t)MROWS * HDIM];
__device__ __half g_qh[(size_t)MROWS * HDIM];       // Q (prescaled 0.125)
__device__ __half g_kh[(size_t)MROWS * HDIM];
__device__ __half g_vh[(size_t)MROWS * HDIM];
__device__ __half g_ctx[(size_t)MROWS * HDIM];
__device__ __half g_attnh[(size_t)MROWS * HDIM];
__device__ __half g_inter[(size_t)MROWS * FFDIM];
__device__ __half g_adder[(size_t)BATCH * SEQ * SEQ];

__device__ __half g_wqkv[(size_t)3 * HDIM * HDIM];  // packed, transposed [N,K]
__device__ __half g_wao[(size_t)HDIM * HDIM];
__device__ __half g_wi[(size_t)FFDIM * HDIM];
__device__ __half g_wo[(size_t)HDIM * FFDIM];

__device__ __forceinline__ float tanh_fast(float x) {
    float y;
    asm("tanh.approx.f32 %0, %1;" : "=f"(y) : "f"(x));
    return y;
}
__device__ __forceinline__ float gelu_tanh(float x) {
    float x3 = x * x * x;
    return 0.5f * x * (1.0f + tanh_fast(0.7978845608028654f * (x + 0.044715f * x3)));
}
__device__ __forceinline__ uint32_t h2_as_u32(__half2 h) {
    union { __half2 h2; uint32_t u; } c; c.h2 = h; return c.u;
}

// ---------------------------------------------------------------------------
// PTX helpers (non-volatile ldm/mma; cp.async volatile)
// ---------------------------------------------------------------------------
__device__ __forceinline__ uint32_t smem_u32(const void* p) {
    uint32_t a;
    asm("{ .reg .u64 t; cvta.to.shared.u64 t, %1; cvt.u32.u64 %0, t; }"
        : "=r"(a) : "l"(p));
    return a;
}
__device__ __forceinline__ void cp16(uint32_t saddr, const void* gaddr) {
    asm volatile("cp.async.cg.shared.global [%0], [%1], 16;" :: "r"(saddr), "l"(gaddr));
}
#define CP_COMMIT() asm volatile("cp.async.commit_group;" ::: "memory")
#define CP_WAIT(n)  asm volatile("cp.async.wait_group %0;" :: "n"(n) : "memory")

__device__ __forceinline__ void ldm_x4(uint32_t* r, uint32_t addr) {
    asm("ldmatrix.sync.aligned.m8n8.x4.shared.b16 {%0,%1,%2,%3}, [%4];"
        : "=r"(r[0]), "=r"(r[1]), "=r"(r[2]), "=r"(r[3]) : "r"(addr) : "memory");
}
__device__ __forceinline__ void ldm_x4_t(uint32_t* r, uint32_t addr) {
    asm("ldmatrix.sync.aligned.m8n8.x4.trans.shared.b16 {%0,%1,%2,%3}, [%4];"
        : "=r"(r[0]), "=r"(r[1]), "=r"(r[2]), "=r"(r[3]) : "r"(addr) : "memory");
}
__device__ __forceinline__ void mma_f16(float* c, const uint32_t* a, const uint32_t* b) {
    asm("mma.sync.aligned.m16n8k16.row.col.f32.f16.f16.f32 "
        "{%0,%1,%2,%3}, {%4,%5,%6,%7}, {%8,%9}, {%0,%1,%2,%3};"
        : "+f"(c[0]), "+f"(c[1]), "+f"(c[2]), "+f"(c[3])
        : "r"(a[0]), "r"(a[1]), "r"(a[2]), "r"(a[3]), "r"(b[0]), "r"(b[1]));
}

// ---------------------------------------------------------------------------
// prep1: input cvt + mask cvt + QKV weight transposes (needed before QKV GEMM)
// Block ranges (256 threads): [0,4096) cvt, [4096,6144) mask, [6144,9216) Wq/Wk/Wv
// ---------------------------------------------------------------------------
#define PREP1_BLOCKS 9216

__global__ __launch_bounds__(256)
void prep1_kernel(const float* __restrict__ inp, const int* __restrict__ mask,
                  const float* __restrict__ Wq, const float* __restrict__ Wk,
                  const float* __restrict__ Wv,
                  __half* __restrict__ xh, __half* __restrict__ adder,
                  __half* __restrict__ wqkv)
{
    __shared__ float tile[32][33];
    const int bid = blockIdx.x;
    const int t = threadIdx.x;

    if (bid < 4096) {
        int i = bid * 256 + t;
        float4 v = ((const float4*)inp)[i];
        union { __half2 h2[2]; uint2 u; } p;
        p.h2[0] = __floats2half2_rn(v.x, v.y);
        p.h2[1] = __floats2half2_rn(v.z, v.w);
        ((uint2*)xh)[i] = p.u;
        return;
    }
    if (bid < 6144) {
        int i = (bid - 4096) * 256 + t;
        int4 v = ((const int4*)mask)[i];
        union { __half2 h2[2]; uint2 u; } p;
        p.h2[0] = __floats2half2_rn((1.0f - (float)v.x) * -10000.0f,
                                    (1.0f - (float)v.y) * -10000.0f);
        p.h2[1] = __floats2half2_rn((1.0f - (float)v.z) * -10000.0f,
                                    (1.0f - (float)v.w) * -10000.0f);
        ((uint2*)adder)[i] = p.u;
        return;
    }

    const float* W;
    __half* T;
    int lb;
    if (bid < 7168)      { W = Wq; T = wqkv;                           lb = bid - 6144; }
    else if (bid < 8192) { W = Wk; T = wqkv + (size_t)HDIM * HDIM;     lb = bid - 7168; }
    else                 { W = Wv; T = wqkv + (size_t)2 * HDIM * HDIM; lb = bid - 8192; }

    const int nbx = HDIM / 32;
    const int bx = lb % nbx;
    const int by = lb / nbx;
    const int tx = t & 31;
    const int ty = t >> 5;

    const int x = bx * 32 + tx;
    const int y0 = by * 32;
    #pragma unroll
    for (int j = 0; j < 32; j += 8)
        tile[ty + j][tx] = W[(size_t)(y0 + ty + j) * HDIM + x];
    __syncthreads();

    const int k = y0 + tx;
    #pragma unroll
    for (int j = 0; j < 32; j += 8) {
        int n = bx * 32 + ty + j;
        T[(size_t)n * HDIM + k] = __float2half_rn(tile[tx][ty + j]);
    }
}

// ---------------------------------------------------------------------------
// prep2 (side stream): Wao/Wi/Wo transposes; consumer is AO GEMM (much later)
// Block ranges: [0,1024) Wao, [1024,5120) Wi, [5120,9216) Wo
// ---------------------------------------------------------------------------
#define PREP2_BLOCKS 9216

__global__ __launch_bounds__(256)
void prep2_kernel(const float* __restrict__ Wao, const float* __restrict__ Wi,
                  const float* __restrict__ Wo,
                  __half* __restrict__ wao, __half* __restrict__ wi,
                  __half* __restrict__ wo)
{
    __shared__ float tile[32][33];
    const int bid = blockIdx.x;
    const int t = threadIdx.x;

    const float* W;
    __half* T;
    int K, N, lb;
    if (bid < 1024)      { W = Wao; T = wao; K = HDIM;  N = HDIM;  lb = bid; }
    else if (bid < 5120) { W = Wi;  T = wi;  K = HDIM;  N = FFDIM; lb = bid - 1024; }
    else                 { W = Wo;  T = wo;  K = FFDIM; N = HDIM;  lb = bid - 5120; }

    const int nbx = N / 32;
    const int bx = lb % nbx;
    const int by = lb / nbx;
    const int tx = t & 31;
    const int ty = t >> 5;

    const int x = bx * 32 + tx;
    const int y0 = by * 32;
    #pragma unroll
    for (int j = 0; j < 32; j += 8)
        tile[ty + j][tx] = W[(size_t)(y0 + ty + j) * N + x];
    __syncthreads();

    const int k = y0 + tx;
    #pragma unroll
    for (int j = 0; j < 32; j += 8) {
        int n = bx * 32 + ty + j;
        T[(size_t)n * K + k] = __float2half_rn(tile[tx][ty + j]);
    }
}

// ---------------------------------------------------------------------------
// fp16 GEMM via mma.sync (proven config: CTA 128x128, 4 warps 2x2, warp 64x64,
// KC=64, 3-stage cp.async, XOR swizzle, interleaved prefetch slices).
// ---------------------------------------------------------------------------
#define KC 64
#define TILE_B 16384
#define STAGE_B (2 * TILE_B)
#define GEMM_SMEM (3 * STAGE_B)

#define SWZ(r, c) ((uint32_t)(r) * 128 + ((uint32_t)((c) ^ ((r) & 7)) * 16))

template<int MODE>
__global__ __launch_bounds__(128, 2)
void mma_gemm(const __half* __restrict__ A, const __half* __restrict__ Bm,
              const float* __restrict__ bias, const float* __restrict__ bias2,
              const float* __restrict__ bias3, const float* __restrict__ res,
              float* __restrict__ Cf, __half* __restrict__ Ch,
              __half* __restrict__ Ch2, __half* __restrict__ Ch3,
              int M, int N, int K, int do_gelu, float oscale)
{
    extern __shared__ char sm[];
    const uint32_t sbase = smem_u32(sm);

    const int t    = threadIdx.x;
    const int lane = t & 31;
    const int w    = t >> 5;
    const int wm   = w & 1;
    const int wn   = w >> 1;
    const int row0 = blockIdx.y * 128;
    const int col0 = blockIdx.x * 128;

    const int NC = K / KC;

    const int l_r = t >> 3;
    const int l_c = t & 7;

    const int a_r  = wm * 64 + (lane & 15);
    const int a_ch = lane >> 4;
    const int b_r  = wn * 64 + (lane >> 4) * 8 + (lane & 7);
    const int b_ch = (lane >> 3) & 1;

    float acc[4][8][4];
    #pragma unroll
    for (int i = 0; i < 4; i++)
        #pragma unroll
        for (int j = 0; j < 8; j++)
            #pragma unroll
            for (int e = 0; e < 4; e++) acc[i][j][e] = 0.0f;

    #pragma unroll
    for (int pc = 0; pc < 2; pc++) {
        const int kofs = pc * KC;
        const uint32_t bb = sbase + pc * STAGE_B;
        #pragma unroll
        for (int j = 0; j < 8; j++) {
            int r = l_r + j * 16;
            uint32_t sw = SWZ(r, l_c);
            cp16(bb + sw,          A  + (size_t)(row0 + r) * K + kofs + l_c * 8);
            cp16(bb + TILE_B + sw, Bm + (size_t)(col0 + r) * K + kofs + l_c * 8);
        }
        CP_COMMIT();
    }

    uint32_t af[2][4][4];
    uint32_t bf[2][16];

    for (int i = 0; i < NC; i++) {
        CP_WAIT(1);
        __syncthreads();

        const uint32_t baseA = sbase + (i % 3) * STAGE_B;
        const uint32_t baseB = baseA + TILE_B;
        const bool do_pf = (i + 2 < NC);
        const int kofs = (i + 2) * KC;
        const uint32_t pb = sbase + ((i + 2) % 3) * STAGE_B;
        const __half* pA = A  + (size_t)(row0 + l_r) * K + kofs + l_c * 8;
        const __half* pB = Bm + (size_t)(col0 + l_r) * K + kofs + l_c * 8;

        #pragma unroll
        for (int p = 0; p < 4; p++)
            ldm_x4(&bf[0][p * 4], baseB + SWZ(b_r + p * 16, b_ch));
        #pragma unroll
        for (int mt = 0; mt < 4; mt++)
            ldm_x4(af[0][mt], baseA + SWZ(a_r + mt * 16, a_ch));

        #pragma unroll
        for (int ks = 0; ks < 4; ks++) {
            const int cur = ks & 1, nxt = cur ^ 1;

            if (do_pf) {
                #pragma unroll
                for (int jj = 0; jj < 2; jj++) {
                    int j = ks * 2 + jj;
                    int r = l_r + j * 16;
                    uint32_t sw = SWZ(r, l_c);
                    cp16(pb + sw,          pA + (size_t)(j * 16) * K);
                    cp16(pb + TILE_B + sw, pB + (size_t)(j * 16) * K);
                }
            }

            if (ks < 3) {
                #pragma unroll
                for (int p = 0; p < 4; p++)
                    ldm_x4(&bf[nxt][p * 4],
                           baseB + SWZ(b_r + p * 16, (ks + 1) * 2 + b_ch));
                #pragma unroll
                for (int mt = 0; mt < 4; mt++)
                    ldm_x4(af[nxt][mt],
                           baseA + SWZ(a_r + mt * 16, (ks + 1) * 2 + a_ch));
            }
            #pragma unroll
            for (int mt = 0; mt < 4; mt++)
                #pragma unroll
                for (int nt = 0; nt < 8; nt++)
                    mma_f16(acc[mt][nt], af[cur][mt], &bf[cur][nt * 2]);
        }
        CP_COMMIT();
    }

    const int qr = lane >> 2;
    const int qc = (lane & 3) * 2;

    if (MODE == 1) {
        const int seg = col0 >> 10;
        const float* bseg = (seg == 0) ? bias : (seg == 1) ? bias2 : bias3;
        __half* outp      = (seg == 0) ? Ch   : (seg == 1) ? Ch2   : Ch3;
        const float osc   = (seg == 0) ? 0.125f : 1.0f;
        #pragma unroll
        for (int mt = 0; mt < 4; mt++) {
            #pragma unroll
            for (int nt = 0; nt < 8; nt++) {
                const int gr0 = row0 + wm * 64 + mt * 16 + qr;
                const int gcl = (col0 & 1023) + wn * 64 + nt * 8 + qc;
                float2 bv = *(const float2*)(bseg + gcl);
                *(__half2*)(outp + (size_t)gr0 * HDIM + gcl) =
                    __floats2half2_rn((acc[mt][nt][0] + bv.x) * osc,
                                      (acc[mt][nt][1] + bv.y) * osc);
                *(__half2*)(outp + (size_t)(gr0 + 8) * HDIM + gcl) =
                    __floats2half2_rn((acc[mt][nt][2] + bv.x) * osc,
                                      (acc[mt][nt][3] + bv.y) * osc);
            }
        }
        return;
    }

    #pragma unroll
    for (int mt = 0; mt < 4; mt++) {
        #pragma unroll
        for (int nt = 0; nt < 8; nt++) {
            const int gr0 = row0 + wm * 64 + mt * 16 + qr;
            const int gc  = col0 + wn * 64 + nt * 8 + qc;
            float2 bv = *(const float2*)(bias + gc);
            float o0 = (acc[mt][nt][0] + bv.x) * oscale;
            float o1 = (acc[mt][nt][1] + bv.y) * oscale;
            float o2 = (acc[mt][nt][2] + bv.x) * oscale;
            float o3 = (acc[mt][nt][3] + bv.y) * oscale;
            if (res) {
                float2 r0v = *(const float2*)(res + (size_t)gr0 * N + gc);
                float2 r1v = *(const float2*)(res + (size_t)(gr0 + 8) * N + gc);
                o0 += r0v.x; o1 += r0v.y; o2 += r1v.x; o3 += r1v.y;
            }
            if (do_gelu) {
                o0 = gelu_tanh(o0); o1 = gelu_tanh(o1);
                o2 = gelu_tanh(o2); o3 = gelu_tanh(o3);
            }
            if (Cf) {
                *(float2*)(Cf + (size_t)gr0 * N + gc)       = make_float2(o0, o1);
                *(float2*)(Cf + (size_t)(gr0 + 8) * N + gc) = make_float2(o2, o3);
            } else {
                *(__half2*)(Ch + (size_t)gr0 * N + gc)       = __floats2half2_rn(o0, o1);
                *(__half2*)(Ch + (size_t)(gr0 + 8) * N + gc) = __floats2half2_rn(o2, o3);
            }
        }
    }
}

// ---------------------------------------------------------------------------
// Tensor-core flash attention (fp16 mma, fp32 softmax/accum). Unchanged.
// ---------------------------------------------------------------------------
#define ALDA 72
#define SQ_OFF   0
#define SK_OFF   9216
#define SV_OFF   36864
#define SAD_OFF  64512
#define ATTN_SMEM 89088

__global__ __launch_bounds__(128)
void attn_kernel(const __half* __restrict__ Qg, const __half* __restrict__ Kg,
                 const __half* __restrict__ Vg, const __half* __restrict__ ADg,
                 __half* __restrict__ O)
{
    extern __shared__ char sm[];
    const uint32_t sbase = smem_u32(sm);

    const int t = threadIdx.x;
    const int lane = t & 31;
    const int w = t >> 5;
    const int b = blockIdx.z, h = blockIdx.y;
    const int q0 = blockIdx.x * 64;

    const int qr = lane >> 2;
    const int qc = (lane & 3) * 2;

    const int lr = t >> 1;
    const int lc2 = (t & 1) * 4;

    auto issue = [&](int ic) {
        const int slot = ic % 3;
        const int kc = ic * 64;
        const __half* kg = Kg + (size_t)(b * SEQ + kc + lr) * HDIM + h * DHEAD;
        const __half* vg = Vg + (size_t)(b * SEQ + kc + lr) * HDIM + h * DHEAD;
        const __half* ag = ADg + (size_t)(b * SEQ + q0 + lr) * SEQ + kc;
        uint32_t ks = sbase + SK_OFF + slot * 9216 + lr * (ALDA * 2);
        uint32_t vs = sbase + SV_OFF + slot * 9216 + lr * (ALDA * 2);
        uint32_t as = sbase + SAD_OFF + slot * 8192 + lr * 128;
        #pragma unroll
        for (int c = 0; c < 4; c++) {
            cp16(ks + (lc2 + c) * 16, kg + (lc2 + c) * 8);
            cp16(vs + (lc2 + c) * 16, vg + (lc2 + c) * 8);
            cp16(as + (lc2 + c) * 16, ag + (lc2 + c) * 8);
        }
    };

    {
        const __half* qg = Qg + (size_t)(b * SEQ + q0 + lr) * HDIM + h * DHEAD;
        uint32_t qs = sbase + SQ_OFF + lr * (ALDA * 2);
        #pragma unroll
        for (int c = 0; c < 4; c++)
            cp16(qs + (lc2 + c) * 16, qg + (lc2 + c) * 8);
        issue(0);
        CP_COMMIT();
        issue(1);
        CP_COMMIT();
    }

    const int a_row = w * 16 + (lane & 15);
    const int a_col = (lane >> 4) * 8;
    const int b_nrow = (lane >> 4) * 8 + (lane & 7);
    const int b_kcol = ((lane >> 3) & 1) * 8;
    const int v_krow = lane & 15;
    const int v_ncol = (lane >> 4) * 8;

    uint32_t qf[4][4];
    float Oa[8][4];
    #pragma unroll
    for (int i = 0; i < 8; i++)
        #pragma unroll
        for (int e = 0; e < 4; e++) Oa[i][e] = 0.0f;
    float m0 = -1e30f, m1 = -1e30f, l0 = 0.0f, l1 = 0.0f;

    for (int ic = 0; ic < 8; ic++) {
        CP_WAIT(1);
        __syncthreads();

        if (ic == 0) {
            #pragma unroll
            for (int ks = 0; ks < 4; ks++) {
                uint32_t off = (uint32_t)a_row * (ALDA * 2) + (ks * 16 + a_col) * 2;
                ldm_x4(qf[ks], sbase + SQ_OFF + off);
            }
        }
        if (ic + 2 < 8) issue(ic + 2);
        CP_COMMIT();

        const int slot = ic % 3;
        const uint32_t baseK = sbase + SK_OFF + slot * 9216;
        const uint32_t baseV = sbase + SV_OFF + slot * 9216;
        const uint32_t baseAD = sbase + SAD_OFF + slot * 8192;

        float s[8][4];
        #pragma unroll
        for (int nt = 0; nt < 8; nt++) {
            uint32_t ad0 = (baseAD - sbase) + ((w * 16 + qr) * 64 + nt * 8 + qc) * 2;
            float2 f0 = __half22float2(*(const __half2*)(sm + ad0));
            float2 f1 = __half22float2(*(const __half2*)(sm + ad0 + 8 * 128));
            s[nt][0] = f0.x; s[nt][1] = f0.y;
            s[nt][2] = f1.x; s[nt][3] = f1.y;
        }
        #pragma unroll
        for (int nb = 0; nb < 4; nb++) {
            #pragma unroll
            for (int ks = 0; ks < 4; ks++) {
                uint32_t bfr[4];
                uint32_t off = (uint32_t)(nb * 16 + b_nrow) * (ALDA * 2)
                             + (ks * 16 + b_kcol) * 2;
                ldm_x4(bfr, baseK + off);
                mma_f16(s[2 * nb],     qf[ks], &bfr[0]);
                mma_f16(s[2 * nb + 1], qf[ks], &bfr[2]);
            }
        }

        float mx0 = -1e30f, mx1 = -1e30f;
        #pragma unroll
        for (int nt = 0; nt < 8; nt++) {
            mx0 = fmaxf(mx0, fmaxf(s[nt][0], s[nt][1]));
            mx1 = fmaxf(mx1, fmaxf(s[nt][2], s[nt][3]));
        }
        mx0 = fmaxf(mx0, __shfl_xor_sync(0xffffffffu, mx0, 1));
        mx0 = fmaxf(mx0, __shfl_xor_sync(0xffffffffu, mx0, 2));
        mx1 = fmaxf(mx1, __shfl_xor_sync(0xffffffffu, mx1, 1));
        mx1 = fmaxf(mx1, __shfl_xor_sync(0xffffffffu, mx1, 2));

        const float m0n = fmaxf(m0, mx0);
        const float m1n = fmaxf(m1, mx1);
        const float al0 = __expf(m0 - m0n);
        const float al1 = __expf(m1 - m1n);

        float sum0 = 0.0f, sum1 = 0.0f;
        uint32_t ph[4][4];
        #pragma unroll
        for (int j = 0; j < 4; j++) {
            float p00 = __expf(s[2 * j][0] - m0n);
            float p01 = __expf(s[2 * j][1] - m0n);
            float p02 = __expf(s[2 * j][2] - m1n);
            float p03 = __expf(s[2 * j][3] - m1n);
            float p10 = __expf(s[2 * j + 1][0] - m0n);
            float p11 = __expf(s[2 * j + 1][1] - m0n);
            float p12 = __expf(s[2 * j + 1][2] - m1n);
            float p13 = __expf(s[2 * j + 1][3] - m1n);
            sum0 += p00 + p01 + p10 + p11;
            sum1 += p02 + p03 + p12 + p13;
            ph[j][0] = h2_as_u32(__floats2half2_rn(p00, p01));
            ph[j][1] = h2_as_u32(__floats2half2_rn(p02, p03));
            ph[j][2] = h2_as_u32(__floats2half2_rn(p10, p11));
            ph[j][3] = h2_as_u32(__floats2half2_rn(p12, p13));
        }
        sum0 += __shfl_xor_sync(0xffffffffu, sum0, 1);
        sum0 += __shfl_xor_sync(0xffffffffu, sum0, 2);
        sum1 += __shfl_xor_sync(0xffffffffu, sum1, 1);
        sum1 += __shfl_xor_sync(0xffffffffu, sum1, 2);

        l0 = l0 * al0 + sum0;
        l1 = l1 * al1 + sum1;
        m0 = m0n; m1 = m1n;

        #pragma unroll
        for (int nt = 0; nt < 8; nt++) {
            Oa[nt][0] *= al0; Oa[nt][1] *= al0;
            Oa[nt][2] *= al1; Oa[nt][3] *= al1;
        }

        #pragma unroll
        for (int j = 0; j < 4; j++) {
            #pragma unroll
            for (int nt2 = 0; nt2 < 4; nt2++) {
                uint32_t vf[4];
                uint32_t off = (uint32_t)(j * 16 + v_krow) * (ALDA * 2)
                             + (nt2 * 16 + v_ncol) * 2;
                ldm_x4_t(vf, baseV + off);
                mma_f16(Oa[2 * nt2],     ph[j], &vf[0]);
                mma_f16(Oa[2 * nt2 + 1], ph[j], &vf[2]);
            }
        }
        __syncthreads();
    }

    const float inv0 = 1.0f / l0;
    const float inv1 = 1.0f / l1;
    const int gr0 = b * SEQ + q0 + w * 16 + qr;
    #pragma unroll
    for (int nt = 0; nt < 8; nt++) {
        const int gc = h * DHEAD + nt * 8 + qc;
        *(__half2*)(O + (size_t)gr0 * HDIM + gc) =
            __floats2half2_rn(Oa[nt][0] * inv0, Oa[nt][1] * inv0);
        *(__half2*)(O + (size_t)(gr0 + 8) * HDIM + gc) =
            __floats2half2_rn(Oa[nt][2] * inv1, Oa[nt][3] * inv1);
    }
}

// ---------------------------------------------------------------------------
// LayerNorm over rows of HDIM=1024; optional fp16 dual output.
// ---------------------------------------------------------------------------
__global__ __launch_bounds__(256)
void ln_kernel(const float* __restrict__ x, const float* __restrict__ gamma,
               const float* __restrict__ beta, float* __restrict__ y,
               __half* __restrict__ yh)
{
    const int row = blockIdx.x;
    const int t = threadIdx.x;
    const float* xr = x + (size_t)row * HDIM;

    float4 v = *(const float4*)(xr + t * 4);
    float s  = v.x + v.y + v.z + v.w;
    float s2 = v.x * v.x + v.y * v.y + v.z * v.z + v.w * v.w;

    #pragma unroll
    for (int o = 16; o > 0; o >>= 1) {
        s  += __shfl_xor_sync(0xffffffffu, s, o);
        s2 += __shfl_xor_sync(0xffffffffu, s2, o);
    }
    __shared__ float ws[8], ws2[8];
    const int w = t >> 5, lane = t & 31;
    if (lane == 0) { ws[w] = s; ws2[w] = s2; }
    __syncthreads();

    float ts = 0.0f, ts2 = 0.0f;
    #pragma unroll
    for (int i = 0; i < 8; i++) { ts += ws[i]; ts2 += ws2[i]; }

    const float mean = ts * (1.0f / HDIM);
    const float var  = ts2 * (1.0f / HDIM) - mean * mean;
    const float rstd = rsqrtf(var + 1e-12f);

    float4 g  = *(const float4*)(gamma + t * 4);
    float4 bb = *(const float4*)(beta  + t * 4);
    float4 o;
    o.x = (v.x - mean) * rstd * g.x + bb.x;
    o.y = (v.y - mean) * rstd * g.y + bb.y;
    o.z = (v.z - mean) * rstd * g.z + bb.z;
    o.w = (v.w - mean) * rstd * g.w + bb.w;
    *(float4*)(y + (size_t)row * HDIM + t * 4) = o;
    if (yh) {
        union { __half2 h2[2]; uint2 u; } p;
        p.h2[0] = __floats2half2_rn(o.x, o.y);
        p.h2[1] = __floats2half2_rn(o.z, o.w);
        ((uint2*)(yh + (size_t)row * HDIM))[t] = p.u;
    }
}

// ---------------------------------------------------------------------------
// Orchestration — prep2 forked onto a static side stream (capture-safe
// fork/join via events).
// ---------------------------------------------------------------------------
extern "C" void kernel_launch(void* const* d_in, const int* in_sizes, int n_in,
                              void* d_out, int out_size)
{
    (void)in_sizes; (void)n_in; (void)out_size;

    const float* inp    = (const float*)d_in[0];
    const int*   mask   = (const int*)  d_in[1];
    const float* Wq     = (const float*)d_in[2];
    const float* bq     = (const float*)d_in[3];
    const float* Wk     = (const float*)d_in[4];
    const float* bk     = (const float*)d_in[5];
    const float* Wv     = (const float*)d_in[6];
    const float* bv     = (const float*)d_in[7];
    const float* Wao    = (const float*)d_in[8];
    const float* bao    = (const float*)d_in[9];
    const float* gamma1 = (const float*)d_in[10];
    const float* beta1  = (const float*)d_in[11];
    const float* Wi     = (const float*)d_in[12];
    const float* bi     = (const float*)d_in[13];
    const float* Wo     = (const float*)d_in[14];
    const float* bo     = (const float*)d_in[15];
    const float* gamma2 = (const float*)d_in[16];
    const float* beta2  = (const float*)d_in[17];
    float* out = (float*)d_out;

    float *t1, *attn;
    cudaGetSymbolAddress((void**)&t1,   g_t1);
    cudaGetSymbolAddress((void**)&attn, g_attn);

    __half *xh, *qh, *kh, *vh, *ctx, *attnh, *inter, *adder;
    __half *wqkv, *wao, *wi, *wo;
    cudaGetSymbolAddress((void**)&xh,    g_xh);
    cudaGetSymbolAddress((void**)&qh,    g_qh);
    cudaGetSymbolAddress((void**)&kh,    g_kh);
    cudaGetSymbolAddress((void**)&vh,    g_vh);
    cudaGetSymbolAddress((void**)&ctx,   g_ctx);
    cudaGetSymbolAddress((void**)&attnh, g_attnh);
    cudaGetSymbolAddress((void**)&inter, g_inter);
    cudaGetSymbolAddress((void**)&adder, g_adder);
    cudaGetSymbolAddress((void**)&wqkv, g_wqkv);
    cudaGetSymbolAddress((void**)&wao,  g_wao);
    cudaGetSymbolAddress((void**)&wi,   g_wi);
    cudaGetSymbolAddress((void**)&wo,   g_wo);

    static cudaStream_t s2 = nullptr;
    static cudaEvent_t evFork = nullptr, evJoin = nullptr;
    if (!s2) {
        cudaStreamCreateWithFlags(&s2, cudaStreamNonBlocking);
        cudaEventCreateWithFlags(&evFork, cudaEventDisableTiming);
        cudaEventCreateWithFlags(&evJoin, cudaEventDisableTiming);
        cudaFuncSetAttribute(mma_gemm<0>, cudaFuncAttributeMaxDynamicSharedMemorySize, GEMM_SMEM);
        cudaFuncSetAttribute(mma_gemm<1>, cudaFuncAttributeMaxDynamicSharedMemorySize, GEMM_SMEM);
        cudaFuncSetAttribute(attn_kernel, cudaFuncAttributeMaxDynamicSharedMemorySize, ATTN_SMEM);
    }

    dim3 blk256(256), blk128(128);

    dim3 gQKV(3 * HDIM / 128, MROWS / 128);   // 24 x 32
    dim3 gH(HDIM / 128, MROWS / 128);         // 8 x 32
    dim3 gF(FFDIM / 128, MROWS / 128);        // 32 x 32

    // fork: prep2 (Wao/Wi/Wo transposes) on side stream
    cudaEventRecord(evFork, 0);
    cudaStreamWaitEvent(s2, evFork, 0);
    prep2_kernel<<<PREP2_BLOCKS, blk256, 0, s2>>>(Wao, Wi, Wo, wao, wi, wo);
    cudaEventRecord(evJoin, s2);

    // main stream: prep1 -> QKV -> attention
    prep1_kernel<<<PREP1_BLOCKS, blk256>>>(inp, mask, Wq, Wk, Wv, xh, adder, wqkv);

    mma_gemm<1><<<gQKV, blk128, GEMM_SMEM>>>(xh, wqkv, bq, bk, bv, nullptr,
                                             nullptr, qh, kh, vh,
                                             MROWS, 3 * HDIM, HDIM, 0, 1.0f);

    attn_kernel<<<dim3(SEQ / 64, NHEAD, BATCH), blk128, ATTN_SMEM>>>(qh, kh, vh, adder, ctx);

    // join before first consumer of wao/wi/wo
    cudaStreamWaitEvent(0, evJoin, 0);

    // AO projection + residual, LN1
    mma_gemm<0><<<gH, blk128, GEMM_SMEM>>>(ctx, wao, bao, nullptr, nullptr, inp,
                                           t1, nullptr, nullptr, nullptr,
                                           MROWS, HDIM, HDIM, 0, 1.0f);
    ln_kernel<<<MROWS, blk256>>>(t1, gamma1, beta1, attn, attnh);

    // FFN
    mma_gemm<0><<<gF, blk128, GEMM_SMEM>>>(attnh, wi, bi, nullptr, nullptr, nullptr,
                                           nullptr, inter, nullptr, nullptr,
                                           MROWS, FFDIM, HDIM, 1, 1.0f);
    mma_gemm<0><<<gH, blk128, GEMM_SMEM>>>(inter, wo, bo, nullptr, nullptr, attn,
                                           t1, nullptr, nullptr, nullptr,
                                           MROWS, HDIM, FFDIM, 0, 1.0f);
    ln_kernel<<<MROWS, blk256>>>(t1, gamma2, beta2, out, nullptr);
}

// round 16
// speedup vs baseline: 1.0501x; 1.0266x over previous
#include <cuda_runtime.h>
#include <cuda_fp16.h>
#include <math.h>
#include <stdint.h>

#define BATCH 8
#define SEQ   512
#define HDIM  1024
#define FFDIM 4096
#define NHEAD 16
#define DHEAD 64
#define MROWS (BATCH*SEQ)   // 4096

// ---------------------------------------------------------------------------
// Static device scratch
// ---------------------------------------------------------------------------
__device__ float g_t1[(size_t)MROWS * HDIM];
__device__ float g_attn[(size_t)MROWS * HDIM];

__device__ __half g_xh[(size_t)MROWS * HDIM];
__device__ __half g_qh[(size_t)MROWS * HDIM];       // Q (prescaled 0.125)
__device__ __half g_kh[(size_t)MROWS * HDIM];
__device__ __half g_vh[(size_t)MROWS * HDIM];
__device__ __half g_ctx[(size_t)MROWS * HDIM];
__device__ __half g_attnh[(size_t)MROWS * HDIM];
__device__ __half g_inter[(size_t)MROWS * FFDIM];
__device__ __half g_adder[(size_t)BATCH * SEQ * SEQ];

__device__ __half g_wqkv[(size_t)3 * HDIM * HDIM];  // packed, transposed [N,K]
__device__ __half g_wao[(size_t)HDIM * HDIM];
__device__ __half g_wi[(size_t)FFDIM * HDIM];
__device__ __half g_wo[(size_t)HDIM * FFDIM];

__device__ __forceinline__ float tanh_fast(float x) {
    float y;
    asm("tanh.approx.f32 %0, %1;" : "=f"(y) : "f"(x));
    return y;
}
__device__ __forceinline__ float gelu_tanh(float x) {
    float x3 = x * x * x;
    return 0.5f * x * (1.0f + tanh_fast(0.7978845608028654f * (x + 0.044715f * x3)));
}
__device__ __forceinline__ uint32_t h2_as_u32(__half2 h) {
    union { __half2 h2; uint32_t u; } c; c.h2 = h; return c.u;
}

// ---------------------------------------------------------------------------
// PTX helpers (non-volatile ldm/mma; cp.async volatile)
// ---------------------------------------------------------------------------
__device__ __forceinline__ uint32_t smem_u32(const void* p) {
    uint32_t a;
    asm("{ .reg .u64 t; cvta.to.shared.u64 t, %1; cvt.u32.u64 %0, t; }"
        : "=r"(a) : "l"(p));
    return a;
}
__device__ __forceinline__ void cp16(uint32_t saddr, const void* gaddr) {
    asm volatile("cp.async.cg.shared.global [%0], [%1], 16;" :: "r"(saddr), "l"(gaddr));
}
#define CP_COMMIT() asm volatile("cp.async.commit_group;" ::: "memory")
#define CP_WAIT(n)  asm volatile("cp.async.wait_group %0;" :: "n"(n) : "memory")

__device__ __forceinline__ void ldm_x4(uint32_t* r, uint32_t addr) {
    asm("ldmatrix.sync.aligned.m8n8.x4.shared.b16 {%0,%1,%2,%3}, [%4];"
        : "=r"(r[0]), "=r"(r[1]), "=r"(r[2]), "=r"(r[3]) : "r"(addr) : "memory");
}
__device__ __forceinline__ void ldm_x4_t(uint32_t* r, uint32_t addr) {
    asm("ldmatrix.sync.aligned.m8n8.x4.trans.shared.b16 {%0,%1,%2,%3}, [%4];"
        : "=r"(r[0]), "=r"(r[1]), "=r"(r[2]), "=r"(r[3]) : "r"(addr) : "memory");
}
__device__ __forceinline__ void mma_f16(float* c, const uint32_t* a, const uint32_t* b) {
    asm("mma.sync.aligned.m16n8k16.row.col.f32.f16.f16.f32 "
        "{%0,%1,%2,%3}, {%4,%5,%6,%7}, {%8,%9}, {%0,%1,%2,%3};"
        : "+f"(c[0]), "+f"(c[1]), "+f"(c[2]), "+f"(c[3])
        : "r"(a[0]), "r"(a[1]), "r"(a[2]), "r"(a[3]), "r"(b[0]), "r"(b[1]));
}

// ---------------------------------------------------------------------------
// prep1: input cvt + mask cvt + QKV weight transposes
// ---------------------------------------------------------------------------
#define PREP1_BLOCKS 9216

__global__ __launch_bounds__(256)
void prep1_kernel(const float* __restrict__ inp, const int* __restrict__ mask,
                  const float* __restrict__ Wq, const float* __restrict__ Wk,
                  const float* __restrict__ Wv,
                  __half* __restrict__ xh, __half* __restrict__ adder,
                  __half* __restrict__ wqkv)
{
    __shared__ float tile[32][33];
    const int bid = blockIdx.x;
    const int t = threadIdx.x;

    if (bid < 4096) {
        int i = bid * 256 + t;
        float4 v = ((const float4*)inp)[i];
        union { __half2 h2[2]; uint2 u; } p;
        p.h2[0] = __floats2half2_rn(v.x, v.y);
        p.h2[1] = __floats2half2_rn(v.z, v.w);
        ((uint2*)xh)[i] = p.u;
        return;
    }
    if (bid < 6144) {
        int i = (bid - 4096) * 256 + t;
        int4 v = ((const int4*)mask)[i];
        union { __half2 h2[2]; uint2 u; } p;
        p.h2[0] = __floats2half2_rn((1.0f - (float)v.x) * -10000.0f,
                                    (1.0f - (float)v.y) * -10000.0f);
        p.h2[1] = __floats2half2_rn((1.0f - (float)v.z) * -10000.0f,
                                    (1.0f - (float)v.w) * -10000.0f);
        ((uint2*)adder)[i] = p.u;
        return;
    }

    const float* W;
    __half* T;
    int lb;
    if (bid < 7168)      { W = Wq; T = wqkv;                           lb = bid - 6144; }
    else if (bid < 8192) { W = Wk; T = wqkv + (size_t)HDIM * HDIM;     lb = bid - 7168; }
    else                 { W = Wv; T = wqkv + (size_t)2 * HDIM * HDIM; lb = bid - 8192; }

    const int nbx = HDIM / 32;
    const int bx = lb % nbx;
    const int by = lb / nbx;
    const int tx = t & 31;
    const int ty = t >> 5;

    const int x = bx * 32 + tx;
    const int y0 = by * 32;
    #pragma unroll
    for (int j = 0; j < 32; j += 8)
        tile[ty + j][tx] = W[(size_t)(y0 + ty + j) * HDIM + x];
    __syncthreads();

    const int k = y0 + tx;
    #pragma unroll
    for (int j = 0; j < 32; j += 8) {
        int n = bx * 32 + ty + j;
        T[(size_t)n * HDIM + k] = __float2half_rn(tile[tx][ty + j]);
    }
}

// ---------------------------------------------------------------------------
// prep2 (side stream): Wao/Wi/Wo transposes
// ---------------------------------------------------------------------------
#define PREP2_BLOCKS 9216

__global__ __launch_bounds__(256)
void prep2_kernel(const float* __restrict__ Wao, const float* __restrict__ Wi,
                  const float* __restrict__ Wo,
                  __half* __restrict__ wao, __half* __restrict__ wi,
                  __half* __restrict__ wo)
{
    __shared__ float tile[32][33];
    const int bid = blockIdx.x;
    const int t = threadIdx.x;

    const float* W;
    __half* T;
    int K, N, lb;
    if (bid < 1024)      { W = Wao; T = wao; K = HDIM;  N = HDIM;  lb = bid; }
    else if (bid < 5120) { W = Wi;  T = wi;  K = HDIM;  N = FFDIM; lb = bid - 1024; }
    else                 { W = Wo;  T = wo;  K = FFDIM; N = HDIM;  lb = bid - 5120; }

    const int nbx = N / 32;
    const int bx = lb % nbx;
    const int by = lb / nbx;
    const int tx = t & 31;
    const int ty = t >> 5;

    const int x = bx * 32 + tx;
    const int y0 = by * 32;
    #pragma unroll
    for (int j = 0; j < 32; j += 8)
        tile[ty + j][tx] = W[(size_t)(y0 + ty + j) * N + x];
    __syncthreads();

    const int k = y0 + tx;
    #pragma unroll
    for (int j = 0; j < 32; j += 8) {
        int n = bx * 32 + ty + j;
        T[(size_t)n * K + k] = __float2half_rn(tile[tx][ty + j]);
    }
}

// ---------------------------------------------------------------------------
// fp16 GEMM via mma.sync (proven config)
// ---------------------------------------------------------------------------
#define KC 64
#define TILE_B 16384
#define STAGE_B (2 * TILE_B)
#define GEMM_SMEM (3 * STAGE_B)

#define SWZ(r, c) ((uint32_t)(r) * 128 + ((uint32_t)((c) ^ ((r) & 7)) * 16))

template<int MODE>
__global__ __launch_bounds__(128, 2)
void mma_gemm(const __half* __restrict__ A, const __half* __restrict__ Bm,
              const float* __restrict__ bias, const float* __restrict__ bias2,
              const float* __restrict__ bias3, const float* __restrict__ res,
              float* __restrict__ Cf, __half* __restrict__ Ch,
              __half* __restrict__ Ch2, __half* __restrict__ Ch3,
              int M, int N, int K, int do_gelu, float oscale)
{
    extern __shared__ char sm[];
    const uint32_t sbase = smem_u32(sm);

    const int t    = threadIdx.x;
    const int lane = t & 31;
    const int w    = t >> 5;
    const int wm   = w & 1;
    const int wn   = w >> 1;
    const int row0 = blockIdx.y * 128;
    const int col0 = blockIdx.x * 128;

    const int NC = K / KC;

    const int l_r = t >> 3;
    const int l_c = t & 7;

    const int a_r  = wm * 64 + (lane & 15);
    const int a_ch = lane >> 4;
    const int b_r  = wn * 64 + (lane >> 4) * 8 + (lane & 7);
    const int b_ch = (lane >> 3) & 1;

    float acc[4][8][4];
    #pragma unroll
    for (int i = 0; i < 4; i++)
        #pragma unroll
        for (int j = 0; j < 8; j++)
            #pragma unroll
            for (int e = 0; e < 4; e++) acc[i][j][e] = 0.0f;

    #pragma unroll
    for (int pc = 0; pc < 2; pc++) {
        const int kofs = pc * KC;
        const uint32_t bb = sbase + pc * STAGE_B;
        #pragma unroll
        for (int j = 0; j < 8; j++) {
            int r = l_r + j * 16;
            uint32_t sw = SWZ(r, l_c);
            cp16(bb + sw,          A  + (size_t)(row0 + r) * K + kofs + l_c * 8);
            cp16(bb + TILE_B + sw, Bm + (size_t)(col0 + r) * K + kofs + l_c * 8);
        }
        CP_COMMIT();
    }

    uint32_t af[2][4][4];
    uint32_t bf[2][16];

    for (int i = 0; i < NC; i++) {
        CP_WAIT(1);
        __syncthreads();

        const uint32_t baseA = sbase + (i % 3) * STAGE_B;
        const uint32_t baseB = baseA + TILE_B;
        const bool do_pf = (i + 2 < NC);
        const int kofs = (i + 2) * KC;
        const uint32_t pb = sbase + ((i + 2) % 3) * STAGE_B;
        const __half* pA = A  + (size_t)(row0 + l_r) * K + kofs + l_c * 8;
        const __half* pB = Bm + (size_t)(col0 + l_r) * K + kofs + l_c * 8;

        #pragma unroll
        for (int p = 0; p < 4; p++)
            ldm_x4(&bf[0][p * 4], baseB + SWZ(b_r + p * 16, b_ch));
        #pragma unroll
        for (int mt = 0; mt < 4; mt++)
            ldm_x4(af[0][mt], baseA + SWZ(a_r + mt * 16, a_ch));

        #pragma unroll
        for (int ks = 0; ks < 4; ks++) {
            const int cur = ks & 1, nxt = cur ^ 1;

            if (do_pf) {
                #pragma unroll
                for (int jj = 0; jj < 2; jj++) {
                    int j = ks * 2 + jj;
                    int r = l_r + j * 16;
                    uint32_t sw = SWZ(r, l_c);
                    cp16(pb + sw,          pA + (size_t)(j * 16) * K);
                    cp16(pb + TILE_B + sw, pB + (size_t)(j * 16) * K);
                }
            }

            if (ks < 3) {
                #pragma unroll
                for (int p = 0; p < 4; p++)
                    ldm_x4(&bf[nxt][p * 4],
                           baseB + SWZ(b_r + p * 16, (ks + 1) * 2 + b_ch));
                #pragma unroll
                for (int mt = 0; mt < 4; mt++)
                    ldm_x4(af[nxt][mt],
                           baseA + SWZ(a_r + mt * 16, (ks + 1) * 2 + a_ch));
            }
            #pragma unroll
            for (int mt = 0; mt < 4; mt++)
                #pragma unroll
                for (int nt = 0; nt < 8; nt++)
                    mma_f16(acc[mt][nt], af[cur][mt], &bf[cur][nt * 2]);
        }
        CP_COMMIT();
    }

    const int qr = lane >> 2;
    const int qc = (lane & 3) * 2;

    if (MODE == 1) {
        const int seg = col0 >> 10;
        const float* bseg = (seg == 0) ? bias : (seg == 1) ? bias2 : bias3;
        __half* outp      = (seg == 0) ? Ch   : (seg == 1) ? Ch2   : Ch3;
        const float osc   = (seg == 0) ? 0.125f : 1.0f;
        #pragma unroll
        for (int mt = 0; mt < 4; mt++) {
            #pragma unroll
            for (int nt = 0; nt < 8; nt++) {
                const int gr0 = row0 + wm * 64 + mt * 16 + qr;
                const int gcl = (col0 & 1023) + wn * 64 + nt * 8 + qc;
                float2 bv = *(const float2*)(bseg + gcl);
                *(__half2*)(outp + (size_t)gr0 * HDIM + gcl) =
                    __floats2half2_rn((acc[mt][nt][0] + bv.x) * osc,
                                      (acc[mt][nt][1] + bv.y) * osc);
                *(__half2*)(outp + (size_t)(gr0 + 8) * HDIM + gcl) =
                    __floats2half2_rn((acc[mt][nt][2] + bv.x) * osc,
                                      (acc[mt][nt][3] + bv.y) * osc);
            }
        }
        return;
    }

    #pragma unroll
    for (int mt = 0; mt < 4; mt++) {
        #pragma unroll
        for (int nt = 0; nt < 8; nt++) {
            const int gr0 = row0 + wm * 64 + mt * 16 + qr;
            const int gc  = col0 + wn * 64 + nt * 8 + qc;
            float2 bv = *(const float2*)(bias + gc);
            float o0 = (acc[mt][nt][0] + bv.x) * oscale;
            float o1 = (acc[mt][nt][1] + bv.y) * oscale;
            float o2 = (acc[mt][nt][2] + bv.x) * oscale;
            float o3 = (acc[mt][nt][3] + bv.y) * oscale;
            if (res) {
                float2 r0v = *(const float2*)(res + (size_t)gr0 * N + gc);
                float2 r1v = *(const float2*)(res + (size_t)(gr0 + 8) * N + gc);
                o0 += r0v.x; o1 += r0v.y; o2 += r1v.x; o3 += r1v.y;
            }
            if (do_gelu) {
                o0 = gelu_tanh(o0); o1 = gelu_tanh(o1);
                o2 = gelu_tanh(o2); o3 = gelu_tanh(o3);
            }
            if (Cf) {
                *(float2*)(Cf + (size_t)gr0 * N + gc)       = make_float2(o0, o1);
                *(float2*)(Cf + (size_t)(gr0 + 8) * N + gc) = make_float2(o2, o3);
            } else {
                *(__half2*)(Ch + (size_t)gr0 * N + gc)       = __floats2half2_rn(o0, o1);
                *(__half2*)(Ch + (size_t)(gr0 + 8) * N + gc) = __floats2half2_rn(o2, o3);
            }
        }
    }
}

// ---------------------------------------------------------------------------
// Tensor-core flash attention. R16: 2-stage K/V/adder ring (smem 62464 ->
// 3 CTAs/SM); prefetch of chunk ic+2 issued after the end-of-chunk sync.
// ---------------------------------------------------------------------------
#define ALDA 72
#define SQ_OFF   0
#define SK_OFF   9216                  // 2 x 9216
#define SV_OFF   27648                 // 2 x 9216
#define SAD_OFF  46080                 // 2 x 8192
#define ATTN_SMEM 62464

__global__ __launch_bounds__(128, 3)
void attn_kernel(const __half* __restrict__ Qg, const __half* __restrict__ Kg,
                 const __half* __restrict__ Vg, const __half* __restrict__ ADg,
                 __half* __restrict__ O)
{
    extern __shared__ char sm[];
    const uint32_t sbase = smem_u32(sm);

    const int t = threadIdx.x;
    const int lane = t & 31;
    const int w = t >> 5;
    const int b = blockIdx.z, h = blockIdx.y;
    const int q0 = blockIdx.x * 64;

    const int qr = lane >> 2;
    const int qc = (lane & 3) * 2;

    const int lr = t >> 1;
    const int lc2 = (t & 1) * 4;

    auto issue = [&](int ic) {
        const int slot = ic & 1;
        const int kc = ic * 64;
        const __half* kg = Kg + (size_t)(b * SEQ + kc + lr) * HDIM + h * DHEAD;
        const __half* vg = Vg + (size_t)(b * SEQ + kc + lr) * HDIM + h * DHEAD;
        const __half* ag = ADg + (size_t)(b * SEQ + q0 + lr) * SEQ + kc;
        uint32_t ks = sbase + SK_OFF + slot * 9216 + lr * (ALDA * 2);
        uint32_t vs = sbase + SV_OFF + slot * 9216 + lr * (ALDA * 2);
        uint32_t as = sbase + SAD_OFF + slot * 8192 + lr * 128;
        #pragma unroll
        for (int c = 0; c < 4; c++) {
            cp16(ks + (lc2 + c) * 16, kg + (lc2 + c) * 8);
            cp16(vs + (lc2 + c) * 16, vg + (lc2 + c) * 8);
            cp16(as + (lc2 + c) * 16, ag + (lc2 + c) * 8);
        }
    };

    {
        const __half* qg = Qg + (size_t)(b * SEQ + q0 + lr) * HDIM + h * DHEAD;
        uint32_t qs = sbase + SQ_OFF + lr * (ALDA * 2);
        #pragma unroll
        for (int c = 0; c < 4; c++)
            cp16(qs + (lc2 + c) * 16, qg + (lc2 + c) * 8);
        issue(0);
        CP_COMMIT();
        issue(1);
        CP_COMMIT();
    }

    const int a_row = w * 16 + (lane & 15);
    const int a_col = (lane >> 4) * 8;
    const int b_nrow = (lane >> 4) * 8 + (lane & 7);
    const int b_kcol = ((lane >> 3) & 1) * 8;
    const int v_krow = lane & 15;
    const int v_ncol = (lane >> 4) * 8;

    uint32_t qf[4][4];
    float Oa[8][4];
    #pragma unroll
    for (int i = 0; i < 8; i++)
        #pragma unroll
        for (int e = 0; e < 4; e++) Oa[i][e] = 0.0f;
    float m0 = -1e30f, m1 = -1e30f, l0 = 0.0f, l1 = 0.0f;

    for (int ic = 0; ic < 8; ic++) {
        CP_WAIT(1);
        __syncthreads();

        if (ic == 0) {
            #pragma unroll
            for (int ks = 0; ks < 4; ks++) {
                uint32_t off = (uint32_t)a_row * (ALDA * 2) + (ks * 16 + a_col) * 2;
                ldm_x4(qf[ks], sbase + SQ_OFF + off);
            }
        }

        const int slot = ic & 1;
        const uint32_t baseK = sbase + SK_OFF + slot * 9216;
        const uint32_t baseV = sbase + SV_OFF + slot * 9216;
        const uint32_t baseAD = sbase + SAD_OFF + slot * 8192;

        float s[8][4];
        #pragma unroll
        for (int nt = 0; nt < 8; nt++) {
            uint32_t ad0 = (baseAD - sbase) + ((w * 16 + qr) * 64 + nt * 8 + qc) * 2;
            float2 f0 = __half22float2(*(const __half2*)(sm + ad0));
            float2 f1 = __half22float2(*(const __half2*)(sm + ad0 + 8 * 128));
            s[nt][0] = f0.x; s[nt][1] = f0.y;
            s[nt][2] = f1.x; s[nt][3] = f1.y;
        }
        #pragma unroll
        for (int nb = 0; nb < 4; nb++) {
            #pragma unroll
            for (int ks = 0; ks < 4; ks++) {
                uint32_t bfr[4];
                uint32_t off = (uint32_t)(nb * 16 + b_nrow) * (ALDA * 2)
                             + (ks * 16 + b_kcol) * 2;
                ldm_x4(bfr, baseK + off);
                mma_f16(s[2 * nb],     qf[ks], &bfr[0]);
                mma_f16(s[2 * nb + 1], qf[ks], &bfr[2]);
            }
        }

        float mx0 = -1e30f, mx1 = -1e30f;
        #pragma unroll
        for (int nt = 0; nt < 8; nt++) {
            mx0 = fmaxf(mx0, fmaxf(s[nt][0], s[nt][1]));
            mx1 = fmaxf(mx1, fmaxf(s[nt][2], s[nt][3]));
        }
        mx0 = fmaxf(mx0, __shfl_xor_sync(0xffffffffu, mx0, 1));
        mx0 = fmaxf(mx0, __shfl_xor_sync(0xffffffffu, mx0, 2));
        mx1 = fmaxf(mx1, __shfl_xor_sync(0xffffffffu, mx1, 1));
        mx1 = fmaxf(mx1, __shfl_xor_sync(0xffffffffu, mx1, 2));

        const float m0n = fmaxf(m0, mx0);
        const float m1n = fmaxf(m1, mx1);
        const float al0 = __expf(m0 - m0n);
        const float al1 = __expf(m1 - m1n);

        float sum0 = 0.0f, sum1 = 0.0f;
        uint32_t ph[4][4];
        #pragma unroll
        for (int j = 0; j < 4; j++) {
            float p00 = __expf(s[2 * j][0] - m0n);
            float p01 = __expf(s[2 * j][1] - m0n);
            float p02 = __expf(s[2 * j][2] - m1n);
            float p03 = __expf(s[2 * j][3] - m1n);
            float p10 = __expf(s[2 * j + 1][0] - m0n);
            float p11 = __expf(s[2 * j + 1][1] - m0n);
            float p12 = __expf(s[2 * j + 1][2] - m1n);
            float p13 = __expf(s[2 * j + 1][3] - m1n);
            sum0 += p00 + p01 + p10 + p11;
            sum1 += p02 + p03 + p12 + p13;
            ph[j][0] = h2_as_u32(__floats2half2_rn(p00, p01));
            ph[j][1] = h2_as_u32(__floats2half2_rn(p02, p03));
            ph[j][2] = h2_as_u32(__floats2half2_rn(p10, p11));
            ph[j][3] = h2_as_u32(__floats2half2_rn(p12, p13));
        }
        sum0 += __shfl_xor_sync(0xffffffffu, sum0, 1);
        sum0 += __shfl_xor_sync(0xffffffffu, sum0, 2);
        sum1 += __shfl_xor_sync(0xffffffffu, sum1, 1);
        sum1 += __shfl_xor_sync(0xffffffffu, sum1, 2);

        l0 = l0 * al0 + sum0;
        l1 = l1 * al1 + sum1;
        m0 = m0n; m1 = m1n;

        #pragma unroll
        for (int nt = 0; nt < 8; nt++) {
            Oa[nt][0] *= al0; Oa[nt][1] *= al0;
            Oa[nt][2] *= al1; Oa[nt][3] *= al1;
        }

        #pragma unroll
        for (int j = 0; j < 4; j++) {
            #pragma unroll
            for (int nt2 = 0; nt2 < 4; nt2++) {
                uint32_t vf[4];
                uint32_t off = (uint32_t)(j * 16 + v_krow) * (ALDA * 2)
                             + (nt2 * 16 + v_ncol) * 2;
                ldm_x4_t(vf, baseV + off);
                mma_f16(Oa[2 * nt2],     ph[j], &vf[0]);
                mma_f16(Oa[2 * nt2 + 1], ph[j], &vf[2]);
            }
        }
        __syncthreads();

        // prefetch chunk ic+2 into the slot just freed (slot ic&1)
        if (ic + 2 < 8) issue(ic + 2);
        CP_COMMIT();
    }

    const float inv0 = 1.0f / l0;
    const float inv1 = 1.0f / l1;
    const int gr0 = b * SEQ + q0 + w * 16 + qr;
    #pragma unroll
    for (int nt = 0; nt < 8; nt++) {
        const int gc = h * DHEAD + nt * 8 + qc;
        *(__half2*)(O + (size_t)gr0 * HDIM + gc) =
            __floats2half2_rn(Oa[nt][0] * inv0, Oa[nt][1] * inv0);
        *(__half2*)(O + (size_t)(gr0 + 8) * HDIM + gc) =
            __floats2half2_rn(Oa[nt][2] * inv1, Oa[nt][3] * inv1);
    }
}

// ---------------------------------------------------------------------------
// LayerNorm over rows of HDIM=1024; optional fp16 dual output.
// ---------------------------------------------------------------------------
__global__ __launch_bounds__(256)
void ln_kernel(const float* __restrict__ x, const float* __restrict__ gamma,
               const float* __restrict__ beta, float* __restrict__ y,
               __half* __restrict__ yh)
{
    const int row = blockIdx.x;
    const int t = threadIdx.x;
    const float* xr = x + (size_t)row * HDIM;

    float4 v = *(const float4*)(xr + t * 4);
    float s  = v.x + v.y + v.z + v.w;
    float s2 = v.x * v.x + v.y * v.y + v.z * v.z + v.w * v.w;

    #pragma unroll
    for (int o = 16; o > 0; o >>= 1) {
        s  += __shfl_xor_sync(0xffffffffu, s, o);
        s2 += __shfl_xor_sync(0xffffffffu, s2, o);
    }
    __shared__ float ws[8], ws2[8];
    const int w = t >> 5, lane = t & 31;
    if (lane == 0) { ws[w] = s; ws2[w] = s2; }
    __syncthreads();

    float ts = 0.0f, ts2 = 0.0f;
    #pragma unroll
    for (int i = 0; i < 8; i++) { ts += ws[i]; ts2 += ws2[i]; }

    const float mean = ts * (1.0f / HDIM);
    const float var  = ts2 * (1.0f / HDIM) - mean * mean;
    const float rstd = rsqrtf(var + 1e-12f);

    float4 g  = *(const float4*)(gamma + t * 4);
    float4 bb = *(const float4*)(beta  + t * 4);
    float4 o;
    o.x = (v.x - mean) * rstd * g.x + bb.x;
    o.y = (v.y - mean) * rstd * g.y + bb.y;
    o.z = (v.z - mean) * rstd * g.z + bb.z;
    o.w = (v.w - mean) * rstd * g.w + bb.w;
    *(float4*)(y + (size_t)row * HDIM + t * 4) = o;
    if (yh) {
        union { __half2 h2[2]; uint2 u; } p;
        p.h2[0] = __floats2half2_rn(o.x, o.y);
        p.h2[1] = __floats2half2_rn(o.z, o.w);
        ((uint2*)(yh + (size_t)row * HDIM))[t] = p.u;
    }
}

// ---------------------------------------------------------------------------
// Orchestration (stream-forked prep2, as in R15)
// ---------------------------------------------------------------------------
extern "C" void kernel_launch(void* const* d_in, const int* in_sizes, int n_in,
                              void* d_out, int out_size)
{
    (void)in_sizes; (void)n_in; (void)out_size;

    const float* inp    = (const float*)d_in[0];
    const int*   mask   = (const int*)  d_in[1];
    const float* Wq     = (const float*)d_in[2];
    const float* bq     = (const float*)d_in[3];
    const float* Wk     = (const float*)d_in[4];
    const float* bk     = (const float*)d_in[5];
    const float* Wv     = (const float*)d_in[6];
    const float* bv     = (const float*)d_in[7];
    const float* Wao    = (const float*)d_in[8];
    const float* bao    = (const float*)d_in[9];
    const float* gamma1 = (const float*)d_in[10];
    const float* beta1  = (const float*)d_in[11];
    const float* Wi     = (const float*)d_in[12];
    const float* bi     = (const float*)d_in[13];
    const float* Wo     = (const float*)d_in[14];
    const float* bo     = (const float*)d_in[15];
    const float* gamma2 = (const float*)d_in[16];
    const float* beta2  = (const float*)d_in[17];
    float* out = (float*)d_out;

    float *t1, *attn;
    cudaGetSymbolAddress((void**)&t1,   g_t1);
    cudaGetSymbolAddress((void**)&attn, g_attn);

    __half *xh, *qh, *kh, *vh, *ctx, *attnh, *inter, *adder;
    __half *wqkv, *wao, *wi, *wo;
    cudaGetSymbolAddress((void**)&xh,    g_xh);
    cudaGetSymbolAddress((void**)&qh,    g_qh);
    cudaGetSymbolAddress((void**)&kh,    g_kh);
    cudaGetSymbolAddress((void**)&vh,    g_vh);
    cudaGetSymbolAddress((void**)&ctx,   g_ctx);
    cudaGetSymbolAddress((void**)&attnh, g_attnh);
    cudaGetSymbolAddress((void**)&inter, g_inter);
    cudaGetSymbolAddress((void**)&adder, g_adder);
    cudaGetSymbolAddress((void**)&wqkv, g_wqkv);
    cudaGetSymbolAddress((void**)&wao,  g_wao);
    cudaGetSymbolAddress((void**)&wi,   g_wi);
    cudaGetSymbolAddress((void**)&wo,   g_wo);

    static cudaStream_t s2 = nullptr;
    static cudaEvent_t evFork = nullptr, evJoin = nullptr;
    if (!s2) {
        cudaStreamCreateWithFlags(&s2, cudaStreamNonBlocking);
        cudaEventCreateWithFlags(&evFork, cudaEventDisableTiming);
        cudaEventCreateWithFlags(&evJoin, cudaEventDisableTiming);
        cudaFuncSetAttribute(mma_gemm<0>, cudaFuncAttributeMaxDynamicSharedMemorySize, GEMM_SMEM);
        cudaFuncSetAttribute(mma_gemm<1>, cudaFuncAttributeMaxDynamicSharedMemorySize, GEMM_SMEM);
        cudaFuncSetAttribute(attn_kernel, cudaFuncAttributeMaxDynamicSharedMemorySize, ATTN_SMEM);
    }

    dim3 blk256(256), blk128(128);

    dim3 gQKV(3 * HDIM / 128, MROWS / 128);   // 24 x 32
    dim3 gH(HDIM / 128, MROWS / 128);         // 8 x 32
    dim3 gF(FFDIM / 128, MROWS / 128);        // 32 x 32

    // fork: prep2 (Wao/Wi/Wo transposes) on side stream
    cudaEventRecord(evFork, 0);
    cudaStreamWaitEvent(s2, evFork, 0);
    prep2_kernel<<<PREP2_BLOCKS, blk256, 0, s2>>>(Wao, Wi, Wo, wao, wi, wo);
    cudaEventRecord(evJoin, s2);

    // main stream: prep1 -> QKV -> attention
    prep1_kernel<<<PREP1_BLOCKS, blk256>>>(inp, mask, Wq, Wk, Wv, xh, adder, wqkv);

    mma_gemm<1><<<gQKV, blk128, GEMM_SMEM>>>(xh, wqkv, bq, bk, bv, nullptr,
                                             nullptr, qh, kh, vh,
                                             MROWS, 3 * HDIM, HDIM, 0, 1.0f);

    attn_kernel<<<dim3(SEQ / 64, NHEAD, BATCH), blk128, ATTN_SMEM>>>(qh, kh, vh, adder, ctx);

    // join before first consumer of wao/wi/wo
    cudaStreamWaitEvent(0, evJoin, 0);

    // AO projection + residual, LN1
    mma_gemm<0><<<gH, blk128, GEMM_SMEM>>>(ctx, wao, bao, nullptr, nullptr, inp,
                                           t1, nullptr, nullptr, nullptr,
                                           MROWS, HDIM, HDIM, 0, 1.0f);
    ln_kernel<<<MROWS, blk256>>>(t1, gamma1, beta1, attn, attnh);

    // FFN
    mma_gemm<0><<<gF, blk128, GEMM_SMEM>>>(attnh, wi, bi, nullptr, nullptr, nullptr,
                                           nullptr, inter, nullptr, nullptr,
                                           MROWS, FFDIM, HDIM, 1, 1.0f);
    mma_gemm<0><<<gH, blk128, GEMM_SMEM>>>(inter, wo, bo, nullptr, nullptr, attn,
                                           t1, nullptr, nullptr, nullptr,
                                           MROWS, HDIM, FFDIM, 0, 1.0f);
    ln_kernel<<<MROWS, blk256>>>(t1, gamma2, beta2, out, nullptr);
}

// round 17
// speedup vs baseline: 1.0585x; 1.0079x over previous
#include <cuda_runtime.h>
#include <cuda_fp16.h>
#include <math.h>
#include <stdint.h>

#define BATCH 8
#define SEQ   512
#define HDIM  1024
#define FFDIM 4096
#define NHEAD 16
#define DHEAD 64
#define MROWS (BATCH*SEQ)   // 4096

// ---------------------------------------------------------------------------
// Static device scratch
// ---------------------------------------------------------------------------
__device__ float g_t1[(size_t)MROWS * HDIM];
__device__ float g_attn[(size_t)MROWS * HDIM];

__device__ __half g_xh[(size_t)MROWS * HDIM];
__device__ __half g_qh[(size_t)MROWS * HDIM];       // Q (prescaled 0.125)
__device__ __half g_kh[(size_t)MROWS * HDIM];
__device__ __half g_vh[(size_t)MROWS * HDIM];
__device__ __half g_ctx[(size_t)MROWS * HDIM];
__device__ __half g_attnh[(size_t)MROWS * HDIM];
__device__ __half g_inter[(size_t)MROWS * FFDIM];
__device__ __half g_adder[(size_t)BATCH * SEQ * SEQ];

__device__ __half g_wqkv[(size_t)3 * HDIM * HDIM];  // packed, transposed [N,K]
__device__ __half g_wao[(size_t)HDIM * HDIM];
__device__ __half g_wi[(size_t)FFDIM * HDIM];
__device__ __half g_wo[(size_t)HDIM * FFDIM];

__device__ __forceinline__ float tanh_fast(float x) {
    float y;
    asm("tanh.approx.f32 %0, %1;" : "=f"(y) : "f"(x));
    return y;
}
__device__ __forceinline__ float gelu_tanh(float x) {
    float x3 = x * x * x;
    return 0.5f * x * (1.0f + tanh_fast(0.7978845608028654f * (x + 0.044715f * x3)));
}
__device__ __forceinline__ uint32_t h2_as_u32(__half2 h) {
    union { __half2 h2; uint32_t u; } c; c.h2 = h; return c.u;
}

// ---------------------------------------------------------------------------
// PTX helpers (non-volatile ldm/mma; cp.async volatile)
// ---------------------------------------------------------------------------
__device__ __forceinline__ uint32_t smem_u32(const void* p) {
    uint32_t a;
    asm("{ .reg .u64 t; cvta.to.shared.u64 t, %1; cvt.u32.u64 %0, t; }"
        : "=r"(a) : "l"(p));
    return a;
}
__device__ __forceinline__ void cp16(uint32_t saddr, const void* gaddr) {
    asm volatile("cp.async.cg.shared.global [%0], [%1], 16;" :: "r"(saddr), "l"(gaddr));
}
#define CP_COMMIT() asm volatile("cp.async.commit_group;" ::: "memory")
#define CP_WAIT(n)  asm volatile("cp.async.wait_group %0;" :: "n"(n) : "memory")

__device__ __forceinline__ void ldm_x4(uint32_t* r, uint32_t addr) {
    asm("ldmatrix.sync.aligned.m8n8.x4.shared.b16 {%0,%1,%2,%3}, [%4];"
        : "=r"(r[0]), "=r"(r[1]), "=r"(r[2]), "=r"(r[3]) : "r"(addr) : "memory");
}
__device__ __forceinline__ void ldm_x4_t(uint32_t* r, uint32_t addr) {
    asm("ldmatrix.sync.aligned.m8n8.x4.trans.shared.b16 {%0,%1,%2,%3}, [%4];"
        : "=r"(r[0]), "=r"(r[1]), "=r"(r[2]), "=r"(r[3]) : "r"(addr) : "memory");
}
__device__ __forceinline__ void mma_f16(float* c, const uint32_t* a, const uint32_t* b) {
    asm("mma.sync.aligned.m16n8k16.row.col.f32.f16.f16.f32 "
        "{%0,%1,%2,%3}, {%4,%5,%6,%7}, {%8,%9}, {%0,%1,%2,%3};"
        : "+f"(c[0]), "+f"(c[1]), "+f"(c[2]), "+f"(c[3])
        : "r"(a[0]), "r"(a[1]), "r"(a[2]), "r"(a[3]), "r"(b[0]), "r"(b[1]));
}

// ---------------------------------------------------------------------------
// prep1: input cvt + mask cvt + QKV weight transposes
// ---------------------------------------------------------------------------
#define PREP1_BLOCKS 9216

__global__ __launch_bounds__(256)
void prep1_kernel(const float* __restrict__ inp, const int* __restrict__ mask,
                  const float* __restrict__ Wq, const float* __restrict__ Wk,
                  const float* __restrict__ Wv,
                  __half* __restrict__ xh, __half* __restrict__ adder,
                  __half* __restrict__ wqkv)
{
    __shared__ float tile[32][33];
    const int bid = blockIdx.x;
    const int t = threadIdx.x;

    if (bid < 4096) {
        int i = bid * 256 + t;
        float4 v = ((const float4*)inp)[i];
        union { __half2 h2[2]; uint2 u; } p;
        p.h2[0] = __floats2half2_rn(v.x, v.y);
        p.h2[1] = __floats2half2_rn(v.z, v.w);
        ((uint2*)xh)[i] = p.u;
        return;
    }
    if (bid < 6144) {
        int i = (bid - 4096) * 256 + t;
        int4 v = ((const int4*)mask)[i];
        union { __half2 h2[2]; uint2 u; } p;
        p.h2[0] = __floats2half2_rn((1.0f - (float)v.x) * -10000.0f,
                                    (1.0f - (float)v.y) * -10000.0f);
        p.h2[1] = __floats2half2_rn((1.0f - (float)v.z) * -10000.0f,
                                    (1.0f - (float)v.w) * -10000.0f);
        ((uint2*)adder)[i] = p.u;
        return;
    }

    const float* W;
    __half* T;
    int lb;
    if (bid < 7168)      { W = Wq; T = wqkv;                           lb = bid - 6144; }
    else if (bid < 8192) { W = Wk; T = wqkv + (size_t)HDIM * HDIM;     lb = bid - 7168; }
    else                 { W = Wv; T = wqkv + (size_t)2 * HDIM * HDIM; lb = bid - 8192; }

    const int nbx = HDIM / 32;
    const int bx = lb % nbx;
    const int by = lb / nbx;
    const int tx = t & 31;
    const int ty = t >> 5;

    const int x = bx * 32 + tx;
    const int y0 = by * 32;
    #pragma unroll
    for (int j = 0; j < 32; j += 8)
        tile[ty + j][tx] = W[(size_t)(y0 + ty + j) * HDIM + x];
    __syncthreads();

    const int k = y0 + tx;
    #pragma unroll
    for (int j = 0; j < 32; j += 8) {
        int n = bx * 32 + ty + j;
        T[(size_t)n * HDIM + k] = __float2half_rn(tile[tx][ty + j]);
    }
}

// ---------------------------------------------------------------------------
// prep2 (side stream): Wao/Wi/Wo transposes
// ---------------------------------------------------------------------------
#define PREP2_BLOCKS 9216

__global__ __launch_bounds__(256)
void prep2_kernel(const float* __restrict__ Wao, const float* __restrict__ Wi,
                  const float* __restrict__ Wo,
                  __half* __restrict__ wao, __half* __restrict__ wi,
                  __half* __restrict__ wo)
{
    __shared__ float tile[32][33];
    const int bid = blockIdx.x;
    const int t = threadIdx.x;

    const float* W;
    __half* T;
    int K, N, lb;
    if (bid < 1024)      { W = Wao; T = wao; K = HDIM;  N = HDIM;  lb = bid; }
    else if (bid < 5120) { W = Wi;  T = wi;  K = HDIM;  N = FFDIM; lb = bid - 1024; }
    else                 { W = Wo;  T = wo;  K = FFDIM; N = HDIM;  lb = bid - 5120; }

    const int nbx = N / 32;
    const int bx = lb % nbx;
    const int by = lb / nbx;
    const int tx = t & 31;
    const int ty = t >> 5;

    const int x = bx * 32 + tx;
    const int y0 = by * 32;
    #pragma unroll
    for (int j = 0; j < 32; j += 8)
        tile[ty + j][tx] = W[(size_t)(y0 + ty + j) * N + x];
    __syncthreads();

    const int k = y0 + tx;
    #pragma unroll
    for (int j = 0; j < 32; j += 8) {
        int n = bx * 32 + ty + j;
        T[(size_t)n * K + k] = __float2half_rn(tile[tx][ty + j]);
    }
}

// ---------------------------------------------------------------------------
// fp16 GEMM via mma.sync (proven config)
// ---------------------------------------------------------------------------
#define KC 64
#define TILE_B 16384
#define STAGE_B (2 * TILE_B)
#define GEMM_SMEM (3 * STAGE_B)

#define SWZ(r, c) ((uint32_t)(r) * 128 + ((uint32_t)((c) ^ ((r) & 7)) * 16))

template<int MODE>
__global__ __launch_bounds__(128, 2)
void mma_gemm(const __half* __restrict__ A, const __half* __restrict__ Bm,
              const float* __restrict__ bias, const float* __restrict__ bias2,
              const float* __restrict__ bias3, const float* __restrict__ res,
              float* __restrict__ Cf, __half* __restrict__ Ch,
              __half* __restrict__ Ch2, __half* __restrict__ Ch3,
              int M, int N, int K, int do_gelu, float oscale)
{
    extern __shared__ char sm[];
    const uint32_t sbase = smem_u32(sm);

    const int t    = threadIdx.x;
    const int lane = t & 31;
    const int w    = t >> 5;
    const int wm   = w & 1;
    const int wn   = w >> 1;
    const int row0 = blockIdx.y * 128;
    const int col0 = blockIdx.x * 128;

    const int NC = K / KC;

    const int l_r = t >> 3;
    const int l_c = t & 7;

    const int a_r  = wm * 64 + (lane & 15);
    const int a_ch = lane >> 4;
    const int b_r  = wn * 64 + (lane >> 4) * 8 + (lane & 7);
    const int b_ch = (lane >> 3) & 1;

    float acc[4][8][4];
    #pragma unroll
    for (int i = 0; i < 4; i++)
        #pragma unroll
        for (int j = 0; j < 8; j++)
            #pragma unroll
            for (int e = 0; e < 4; e++) acc[i][j][e] = 0.0f;

    #pragma unroll
    for (int pc = 0; pc < 2; pc++) {
        const int kofs = pc * KC;
        const uint32_t bb = sbase + pc * STAGE_B;
        #pragma unroll
        for (int j = 0; j < 8; j++) {
            int r = l_r + j * 16;
            uint32_t sw = SWZ(r, l_c);
            cp16(bb + sw,          A  + (size_t)(row0 + r) * K + kofs + l_c * 8);
            cp16(bb + TILE_B + sw, Bm + (size_t)(col0 + r) * K + kofs + l_c * 8);
        }
        CP_COMMIT();
    }

    uint32_t af[2][4][4];
    uint32_t bf[2][16];

    for (int i = 0; i < NC; i++) {
        CP_WAIT(1);
        __syncthreads();

        const uint32_t baseA = sbase + (i % 3) * STAGE_B;
        const uint32_t baseB = baseA + TILE_B;
        const bool do_pf = (i + 2 < NC);
        const int kofs = (i + 2) * KC;
        const uint32_t pb = sbase + ((i + 2) % 3) * STAGE_B;
        const __half* pA = A  + (size_t)(row0 + l_r) * K + kofs + l_c * 8;
        const __half* pB = Bm + (size_t)(col0 + l_r) * K + kofs + l_c * 8;

        #pragma unroll
        for (int p = 0; p < 4; p++)
            ldm_x4(&bf[0][p * 4], baseB + SWZ(b_r + p * 16, b_ch));
        #pragma unroll
        for (int mt = 0; mt < 4; mt++)
            ldm_x4(af[0][mt], baseA + SWZ(a_r + mt * 16, a_ch));

        #pragma unroll
        for (int ks = 0; ks < 4; ks++) {
            const int cur = ks & 1, nxt = cur ^ 1;

            if (do_pf) {
                #pragma unroll
                for (int jj = 0; jj < 2; jj++) {
                    int j = ks * 2 + jj;
                    int r = l_r + j * 16;
                    uint32_t sw = SWZ(r, l_c);
                    cp16(pb + sw,          pA + (size_t)(j * 16) * K);
                    cp16(pb + TILE_B + sw, pB + (size_t)(j * 16) * K);
                }
            }

            if (ks < 3) {
                #pragma unroll
                for (int p = 0; p < 4; p++)
                    ldm_x4(&bf[nxt][p * 4],
                           baseB + SWZ(b_r + p * 16, (ks + 1) * 2 + b_ch));
                #pragma unroll
                for (int mt = 0; mt < 4; mt++)
                    ldm_x4(af[nxt][mt],
                           baseA + SWZ(a_r + mt * 16, (ks + 1) * 2 + a_ch));
            }
            #pragma unroll
            for (int mt = 0; mt < 4; mt++)
                #pragma unroll
                for (int nt = 0; nt < 8; nt++)
                    mma_f16(acc[mt][nt], af[cur][mt], &bf[cur][nt * 2]);
        }
        CP_COMMIT();
    }

    const int qr = lane >> 2;
    const int qc = (lane & 3) * 2;

    if (MODE == 1) {
        const int seg = col0 >> 10;
        const float* bseg = (seg == 0) ? bias : (seg == 1) ? bias2 : bias3;
        __half* outp      = (seg == 0) ? Ch   : (seg == 1) ? Ch2   : Ch3;
        const float osc   = (seg == 0) ? 0.125f : 1.0f;
        #pragma unroll
        for (int mt = 0; mt < 4; mt++) {
            #pragma unroll
            for (int nt = 0; nt < 8; nt++) {
                const int gr0 = row0 + wm * 64 + mt * 16 + qr;
                const int gcl = (col0 & 1023) + wn * 64 + nt * 8 + qc;
                float2 bv = *(const float2*)(bseg + gcl);
                *(__half2*)(outp + (size_t)gr0 * HDIM + gcl) =
                    __floats2half2_rn((acc[mt][nt][0] + bv.x) * osc,
                                      (acc[mt][nt][1] + bv.y) * osc);
                *(__half2*)(outp + (size_t)(gr0 + 8) * HDIM + gcl) =
                    __floats2half2_rn((acc[mt][nt][2] + bv.x) * osc,
                                      (acc[mt][nt][3] + bv.y) * osc);
            }
        }
        return;
    }

    #pragma unroll
    for (int mt = 0; mt < 4; mt++) {
        #pragma unroll
        for (int nt = 0; nt < 8; nt++) {
            const int gr0 = row0 + wm * 64 + mt * 16 + qr;
            const int gc  = col0 + wn * 64 + nt * 8 + qc;
            float2 bv = *(const float2*)(bias + gc);
            float o0 = (acc[mt][nt][0] + bv.x) * oscale;
            float o1 = (acc[mt][nt][1] + bv.y) * oscale;
            float o2 = (acc[mt][nt][2] + bv.x) * oscale;
            float o3 = (acc[mt][nt][3] + bv.y) * oscale;
            if (res) {
                float2 r0v = *(const float2*)(res + (size_t)gr0 * N + gc);
                float2 r1v = *(const float2*)(res + (size_t)(gr0 + 8) * N + gc);
                o0 += r0v.x; o1 += r0v.y; o2 += r1v.x; o3 += r1v.y;
            }
            if (do_gelu) {
                o0 = gelu_tanh(o0); o1 = gelu_tanh(o1);
                o2 = gelu_tanh(o2); o3 = gelu_tanh(o3);
            }
            if (Cf) {
                *(float2*)(Cf + (size_t)gr0 * N + gc)       = make_float2(o0, o1);
                *(float2*)(Cf + (size_t)(gr0 + 8) * N + gc) = make_float2(o2, o3);
            } else {
                *(__half2*)(Ch + (size_t)gr0 * N + gc)       = __floats2half2_rn(o0, o1);
                *(__half2*)(Ch + (size_t)(gr0 + 8) * N + gc) = __floats2half2_rn(o2, o3);
            }
        }
    }
}

// ---------------------------------------------------------------------------
// Tensor-core flash attention. R17: Q fragments loaded straight from global
// memory (no Q smem) -> smem 53248 B -> 4 CTAs/SM. 2-stage K/V/adder ring.
// ---------------------------------------------------------------------------
#define ALDA 72
#define SK_OFF   0                      // 2 x 9216
#define SV_OFF   18432                  // 2 x 9216
#define SAD_OFF  36864                  // 2 x 8192
#define ATTN_SMEM 53248

__global__ __launch_bounds__(128, 4)
void attn_kernel(const __half* __restrict__ Qg, const __half* __restrict__ Kg,
                 const __half* __restrict__ Vg, const __half* __restrict__ ADg,
                 __half* __restrict__ O)
{
    extern __shared__ char sm[];
    const uint32_t sbase = smem_u32(sm);

    const int t = threadIdx.x;
    const int lane = t & 31;
    const int w = t >> 5;
    const int b = blockIdx.z, h = blockIdx.y;
    const int q0 = blockIdx.x * 64;

    const int qr = lane >> 2;
    const int qc = (lane & 3) * 2;

    const int lr = t >> 1;
    const int lc2 = (t & 1) * 4;

    auto issue = [&](int ic) {
        const int slot = ic & 1;
        const int kc = ic * 64;
        const __half* kg = Kg + (size_t)(b * SEQ + kc + lr) * HDIM + h * DHEAD;
        const __half* vg = Vg + (size_t)(b * SEQ + kc + lr) * HDIM + h * DHEAD;
        const __half* ag = ADg + (size_t)(b * SEQ + q0 + lr) * SEQ + kc;
        uint32_t ks = sbase + SK_OFF + slot * 9216 + lr * (ALDA * 2);
        uint32_t vs = sbase + SV_OFF + slot * 9216 + lr * (ALDA * 2);
        uint32_t as = sbase + SAD_OFF + slot * 8192 + lr * 128;
        #pragma unroll
        for (int c = 0; c < 4; c++) {
            cp16(ks + (lc2 + c) * 16, kg + (lc2 + c) * 8);
            cp16(vs + (lc2 + c) * 16, vg + (lc2 + c) * 8);
            cp16(as + (lc2 + c) * 16, ag + (lc2 + c) * 8);
        }
    };

    // prologue: K/V/adder chunks 0,1 via cp.async
    issue(0);
    CP_COMMIT();
    issue(1);
    CP_COMMIT();

    // Q fragments: load directly from global (analytic m16n8k16 A-frag map).
    // a0=(r,c), a1=(r+8,c), a2=(r,c+8), a3=(r+8,c+8); r,c local to warp tile.
    uint32_t qf[4][4];
    {
        const int grow = b * SEQ + q0 + w * 16 + qr;
        const __half* qbase = Qg + (size_t)grow * HDIM + h * DHEAD + qc;
        #pragma unroll
        for (int ks = 0; ks < 4; ks++) {
            const __half* p = qbase + ks * 16;
            qf[ks][0] = h2_as_u32(*(const __half2*)(p));
            qf[ks][1] = h2_as_u32(*(const __half2*)(p + 8 * HDIM));
            qf[ks][2] = h2_as_u32(*(const __half2*)(p + 8));
            qf[ks][3] = h2_as_u32(*(const __half2*)(p + 8 * HDIM + 8));
        }
    }

    const int b_nrow = (lane >> 4) * 8 + (lane & 7);
    const int b_kcol = ((lane >> 3) & 1) * 8;
    const int v_krow = lane & 15;
    const int v_ncol = (lane >> 4) * 8;

    float Oa[8][4];
    #pragma unroll
    for (int i = 0; i < 8; i++)
        #pragma unroll
        for (int e = 0; e < 4; e++) Oa[i][e] = 0.0f;
    float m0 = -1e30f, m1 = -1e30f, l0 = 0.0f, l1 = 0.0f;

    for (int ic = 0; ic < 8; ic++) {
        CP_WAIT(1);
        __syncthreads();

        const int slot = ic & 1;
        const uint32_t baseK = sbase + SK_OFF + slot * 9216;
        const uint32_t baseV = sbase + SV_OFF + slot * 9216;
        const uint32_t baseAD = sbase + SAD_OFF + slot * 8192;

        float s[8][4];
        #pragma unroll
        for (int nt = 0; nt < 8; nt++) {
            uint32_t ad0 = (baseAD - sbase) + ((w * 16 + qr) * 64 + nt * 8 + qc) * 2;
            float2 f0 = __half22float2(*(const __half2*)(sm + ad0));
            float2 f1 = __half22float2(*(const __half2*)(sm + ad0 + 8 * 128));
            s[nt][0] = f0.x; s[nt][1] = f0.y;
            s[nt][2] = f1.x; s[nt][3] = f1.y;
        }
        #pragma unroll
        for (int nb = 0; nb < 4; nb++) {
            #pragma unroll
            for (int ks = 0; ks < 4; ks++) {
                uint32_t bfr[4];
                uint32_t off = (uint32_t)(nb * 16 + b_nrow) * (ALDA * 2)
                             + (ks * 16 + b_kcol) * 2;
                ldm_x4(bfr, baseK + off);
                mma_f16(s[2 * nb],     qf[ks], &bfr[0]);
                mma_f16(s[2 * nb + 1], qf[ks], &bfr[2]);
            }
        }

        float mx0 = -1e30f, mx1 = -1e30f;
        #pragma unroll
        for (int nt = 0; nt < 8; nt++) {
            mx0 = fmaxf(mx0, fmaxf(s[nt][0], s[nt][1]));
            mx1 = fmaxf(mx1, fmaxf(s[nt][2], s[nt][3]));
        }
        mx0 = fmaxf(mx0, __shfl_xor_sync(0xffffffffu, mx0, 1));
        mx0 = fmaxf(mx0, __shfl_xor_sync(0xffffffffu, mx0, 2));
        mx1 = fmaxf(mx1, __shfl_xor_sync(0xffffffffu, mx1, 1));
        mx1 = fmaxf(mx1, __shfl_xor_sync(0xffffffffu, mx1, 2));

        const float m0n = fmaxf(m0, mx0);
        const float m1n = fmaxf(m1, mx1);
        const float al0 = __expf(m0 - m0n);
        const float al1 = __expf(m1 - m1n);

        float sum0 = 0.0f, sum1 = 0.0f;
        uint32_t ph[4][4];
        #pragma unroll
        for (int j = 0; j < 4; j++) {
            float p00 = __expf(s[2 * j][0] - m0n);
            float p01 = __expf(s[2 * j][1] - m0n);
            float p02 = __expf(s[2 * j][2] - m1n);
            float p03 = __expf(s[2 * j][3] - m1n);
            float p10 = __expf(s[2 * j + 1][0] - m0n);
            float p11 = __expf(s[2 * j + 1][1] - m0n);
            float p12 = __expf(s[2 * j + 1][2] - m1n);
            float p13 = __expf(s[2 * j + 1][3] - m1n);
            sum0 += p00 + p01 + p10 + p11;
            sum1 += p02 + p03 + p12 + p13;
            ph[j][0] = h2_as_u32(__floats2half2_rn(p00, p01));
            ph[j][1] = h2_as_u32(__floats2half2_rn(p02, p03));
            ph[j][2] = h2_as_u32(__floats2half2_rn(p10, p11));
            ph[j][3] = h2_as_u32(__floats2half2_rn(p12, p13));
        }
        sum0 += __shfl_xor_sync(0xffffffffu, sum0, 1);
        sum0 += __shfl_xor_sync(0xffffffffu, sum0, 2);
        sum1 += __shfl_xor_sync(0xffffffffu, sum1, 1);
        sum1 += __shfl_xor_sync(0xffffffffu, sum1, 2);

        l0 = l0 * al0 + sum0;
        l1 = l1 * al1 + sum1;
        m0 = m0n; m1 = m1n;

        #pragma unroll
        for (int nt = 0; nt < 8; nt++) {
            Oa[nt][0] *= al0; Oa[nt][1] *= al0;
            Oa[nt][2] *= al1; Oa[nt][3] *= al1;
        }

        #pragma unroll
        for (int j = 0; j < 4; j++) {
            #pragma unroll
            for (int nt2 = 0; nt2 < 4; nt2++) {
                uint32_t vf[4];
                uint32_t off = (uint32_t)(j * 16 + v_krow) * (ALDA * 2)
                             + (nt2 * 16 + v_ncol) * 2;
                ldm_x4_t(vf, baseV + off);
                mma_f16(Oa[2 * nt2],     ph[j], &vf[0]);
                mma_f16(Oa[2 * nt2 + 1], ph[j], &vf[2]);
            }
        }
        __syncthreads();

        if (ic + 2 < 8) issue(ic + 2);
        CP_COMMIT();
    }

    const float inv0 = 1.0f / l0;
    const float inv1 = 1.0f / l1;
    const int gr0 = b * SEQ + q0 + w * 16 + qr;
    #pragma unroll
    for (int nt = 0; nt < 8; nt++) {
        const int gc = h * DHEAD + nt * 8 + qc;
        *(__half2*)(O + (size_t)gr0 * HDIM + gc) =
            __floats2half2_rn(Oa[nt][0] * inv0, Oa[nt][1] * inv0);
        *(__half2*)(O + (size_t)(gr0 + 8) * HDIM + gc) =
            __floats2half2_rn(Oa[nt][2] * inv1, Oa[nt][3] * inv1);
    }
}

// ---------------------------------------------------------------------------
// LayerNorm over rows of HDIM=1024; optional fp16 dual output.
// ---------------------------------------------------------------------------
__global__ __launch_bounds__(256)
void ln_kernel(const float* __restrict__ x, const float* __restrict__ gamma,
               const float* __restrict__ beta, float* __restrict__ y,
               __half* __restrict__ yh)
{
    const int row = blockIdx.x;
    const int t = threadIdx.x;
    const float* xr = x + (size_t)row * HDIM;

    float4 v = *(const float4*)(xr + t * 4);
    float s  = v.x + v.y + v.z + v.w;
    float s2 = v.x * v.x + v.y * v.y + v.z * v.z + v.w * v.w;

    #pragma unroll
    for (int o = 16; o > 0; o >>= 1) {
        s  += __shfl_xor_sync(0xffffffffu, s, o);
        s2 += __shfl_xor_sync(0xffffffffu, s2, o);
    }
    __shared__ float ws[8], ws2[8];
    const int w = t >> 5, lane = t & 31;
    if (lane == 0) { ws[w] = s; ws2[w] = s2; }
    __syncthreads();

    float ts = 0.0f, ts2 = 0.0f;
    #pragma unroll
    for (int i = 0; i < 8; i++) { ts += ws[i]; ts2 += ws2[i]; }

    const float mean = ts * (1.0f / HDIM);
    const float var  = ts2 * (1.0f / HDIM) - mean * mean;
    const float rstd = rsqrtf(var + 1e-12f);

    float4 g  = *(const float4*)(gamma + t * 4);
    float4 bb = *(const float4*)(beta  + t * 4);
    float4 o;
    o.x = (v.x - mean) * rstd * g.x + bb.x;
    o.y = (v.y - mean) * rstd * g.y + bb.y;
    o.z = (v.z - mean) * rstd * g.z + bb.z;
    o.w = (v.w - mean) * rstd * g.w + bb.w;
    *(float4*)(y + (size_t)row * HDIM + t * 4) = o;
    if (yh) {
        union { __half2 h2[2]; uint2 u; } p;
        p.h2[0] = __floats2half2_rn(o.x, o.y);
        p.h2[1] = __floats2half2_rn(o.z, o.w);
        ((uint2*)(yh + (size_t)row * HDIM))[t] = p.u;
    }
}

// ---------------------------------------------------------------------------
// Orchestration (stream-forked prep2)
// ---------------------------------------------------------------------------
extern "C" void kernel_launch(void* const* d_in, const int* in_sizes, int n_in,
                              void* d_out, int out_size)
{
    (void)in_sizes; (void)n_in; (void)out_size;

    const float* inp    = (const float*)d_in[0];
    const int*   mask   = (const int*)  d_in[1];
    const float* Wq     = (const float*)d_in[2];
    const float* bq     = (const float*)d_in[3];
    const float* Wk     = (const float*)d_in[4];
    const float* bk     = (const float*)d_in[5];
    const float* Wv     = (const float*)d_in[6];
    const float* bv     = (const float*)d_in[7];
    const float* Wao    = (const float*)d_in[8];
    const float* bao    = (const float*)d_in[9];
    const float* gamma1 = (const float*)d_in[10];
    const float* beta1  = (const float*)d_in[11];
    const float* Wi     = (const float*)d_in[12];
    const float* bi     = (const float*)d_in[13];
    const float* Wo     = (const float*)d_in[14];
    const float* bo     = (const float*)d_in[15];
    const float* gamma2 = (const float*)d_in[16];
    const float* beta2  = (const float*)d_in[17];
    float* out = (float*)d_out;

    float *t1, *attn;
    cudaGetSymbolAddress((void**)&t1,   g_t1);
    cudaGetSymbolAddress((void**)&attn, g_attn);

    __half *xh, *qh, *kh, *vh, *ctx, *attnh, *inter, *adder;
    __half *wqkv, *wao, *wi, *wo;
    cudaGetSymbolAddress((void**)&xh,    g_xh);
    cudaGetSymbolAddress((void**)&qh,    g_qh);
    cudaGetSymbolAddress((void**)&kh,    g_kh);
    cudaGetSymbolAddress((void**)&vh,    g_vh);
    cudaGetSymbolAddress((void**)&ctx,   g_ctx);
    cudaGetSymbolAddress((void**)&attnh, g_attnh);
    cudaGetSymbolAddress((void**)&inter, g_inter);
    cudaGetSymbolAddress((void**)&adder, g_adder);
    cudaGetSymbolAddress((void**)&wqkv, g_wqkv);
    cudaGetSymbolAddress((void**)&wao,  g_wao);
    cudaGetSymbolAddress((void**)&wi,   g_wi);
    cudaGetSymbolAddress((void**)&wo,   g_wo);

    static cudaStream_t s2 = nullptr;
    static cudaEvent_t evFork = nullptr, evJoin = nullptr;
    if (!s2) {
        cudaStreamCreateWithFlags(&s2, cudaStreamNonBlocking);
        cudaEventCreateWithFlags(&evFork, cudaEventDisableTiming);
        cudaEventCreateWithFlags(&evJoin, cudaEventDisableTiming);
        cudaFuncSetAttribute(mma_gemm<0>, cudaFuncAttributeMaxDynamicSharedMemorySize, GEMM_SMEM);
        cudaFuncSetAttribute(mma_gemm<1>, cudaFuncAttributeMaxDynamicSharedMemorySize, GEMM_SMEM);
        cudaFuncSetAttribute(attn_kernel, cudaFuncAttributeMaxDynamicSharedMemorySize, ATTN_SMEM);
    }

    dim3 blk256(256), blk128(128);

    dim3 gQKV(3 * HDIM / 128, MROWS / 128);   // 24 x 32
    dim3 gH(HDIM / 128, MROWS / 128);         // 8 x 32
    dim3 gF(FFDIM / 128, MROWS / 128);        // 32 x 32

    // fork: prep2 (Wao/Wi/Wo transposes) on side stream
    cudaEventRecord(evFork, 0);
    cudaStreamWaitEvent(s2, evFork, 0);
    prep2_kernel<<<PREP2_BLOCKS, blk256, 0, s2>>>(Wao, Wi, Wo, wao, wi, wo);
    cudaEventRecord(evJoin, s2);

    // main stream: prep1 -> QKV -> attention
    prep1_kernel<<<PREP1_BLOCKS, blk256>>>(inp, mask, Wq, Wk, Wv, xh, adder, wqkv);

    mma_gemm<1><<<gQKV, blk128, GEMM_SMEM>>>(xh, wqkv, bq, bk, bv, nullptr,
                                             nullptr, qh, kh, vh,
                                             MROWS, 3 * HDIM, HDIM, 0, 1.0f);

    attn_kernel<<<dim3(SEQ / 64, NHEAD, BATCH), blk128, ATTN_SMEM>>>(qh, kh, vh, adder, ctx);

    // join before first consumer of wao/wi/wo
    cudaStreamWaitEvent(0, evJoin, 0);

    // AO projection + residual, LN1
    mma_gemm<0><<<gH, blk128, GEMM_SMEM>>>(ctx, wao, bao, nullptr, nullptr, inp,
                                           t1, nullptr, nullptr, nullptr,
                                           MROWS, HDIM, HDIM, 0, 1.0f);
    ln_kernel<<<MROWS, blk256>>>(t1, gamma1, beta1, attn, attnh);

    // FFN
    mma_gemm<0><<<gF, blk128, GEMM_SMEM>>>(attnh, wi, bi, nullptr, nullptr, nullptr,
                                           nullptr, inter, nullptr, nullptr,
                                           MROWS, FFDIM, HDIM, 1, 1.0f);
    mma_gemm<0><<<gH, blk128, GEMM_SMEM>>>(inter, wo, bo, nullptr, nullptr, attn,
                                           t1, nullptr, nullptr, nullptr,
                                           MROWS, HDIM, FFDIM, 0, 1.0f);
    ln_kernel<<<MROWS, blk256>>>(t1, gamma2, beta2, out, nullptr);
}